// round 11
// baseline (speedup 1.0000x reference)
#include <cuda_runtime.h>
#include <cuda_bf16.h>
#include <stdint.h>
#include <math.h>

#define Bn 4
#define Nn 1024
#define Dn 1024
#define NHn 16
#define HDn 64
#define FFHn 2816
#define MOEHn 2048
#define NEn 8
#define CAPn 160
#define TOK (Bn*Nn)
#define NSLOT (NEn*Bn*CAPn)

#define QKV_OFF 0LL
#define WO_OFF  9437184LL
#define W13_OFF 12582912LL
#define W13_STR 5767168LL
#define W2_OFF  29884416LL
#define MW1_OFF 38535168LL
#define MW2_OFF 72089600LL
#define WTOTAL  105644032LL

typedef unsigned long long u64t;

static __device__ float g_norm[TOK*Dn];
static __device__ __nv_bfloat16 g_normh[TOK*Dn], g_norml[TOK*Dn];
static __device__ float g_big [TOK*3*Dn];
static __device__ __nv_bfloat16 g_attnh[TOK*Dn], g_attnl[TOK*Dn];
static __device__ float g_h13[TOK*2*FFHn];
static __device__ __nv_bfloat16 g_hidh[TOK*FFHn], g_hidl[TOK*FFHn];
static __device__ __nv_bfloat16 g_xeh[NSLOT*Dn], g_xel[NSLOT*Dn];
static __device__ float g_ye[NSLOT*Dn];
static __device__ float g_raw [TOK*NEn];
static __device__ int   g_idx1[TOK], g_idx2[TOK], g_keep[TOK];
static __device__ int   g_slot1[TOK], g_slot2[TOK];
static __device__ float g_g1[TOK], g_g2[TOK];
static __device__ float g_rawsum[Bn*NEn], g_cnt1[Bn*NEn];
static __device__ float g_lossbuf[1];
static __device__ __nv_bfloat16 g_whi[WTOTAL];
static __device__ __nv_bfloat16 g_wlo[WTOTAL];

__host__ __device__ __forceinline__ void threefry2x32(unsigned k0, unsigned k1,
                                                      unsigned& x0, unsigned& x1)
{
    unsigned ks2 = k0 ^ k1 ^ 0x1BD11BDAu;
    x0 += k0; x1 += k1;
#define TFR(r) { x0 += x1; x1 = (x1<<(r))|(x1>>(32-(r))); x1 ^= x0; }
    TFR(13) TFR(15) TFR(26) TFR(6)
    x0 += k1;  x1 += ks2 + 1u;
    TFR(17) TFR(29) TFR(16) TFR(24)
    x0 += ks2; x1 += k0 + 2u;
    TFR(13) TFR(15) TFR(26) TFR(6)
    x0 += k0;  x1 += k1 + 3u;
    TFR(17) TFR(29) TFR(16) TFR(24)
    x0 += k1;  x1 += ks2 + 4u;
    TFR(13) TFR(15) TFR(26) TFR(6)
    x0 += ks2; x1 += k0 + 5u;
#undef TFR
}

__global__ void wprep_kernel(const float* __restrict__ W, __nv_bfloat16* __restrict__ hi,
                             __nv_bfloat16* __restrict__ lo, int K, int N,
                             long long sW, long long sO)
{
    __shared__ float t[32][33];
    W  += (long long)blockIdx.z * sW;
    hi += (long long)blockIdx.z * sO;
    lo += (long long)blockIdx.z * sO;
    int n0 = blockIdx.x * 32, k0 = blockIdx.y * 32;
#pragma unroll
    for (int j = 0; j < 4; j++)
        t[threadIdx.y + j*8][threadIdx.x] =
            W[(size_t)(k0 + threadIdx.y + j*8) * N + n0 + threadIdx.x];
    __syncthreads();
#pragma unroll
    for (int j = 0; j < 4; j++) {
        int n = n0 + threadIdx.y + j*8, k = k0 + threadIdx.x;
        float v = t[threadIdx.x][threadIdx.y + j*8];
        __nv_bfloat16 h = __float2bfloat16(v);
        hi[(size_t)n * K + k] = h;
        lo[(size_t)n * K + k] = __float2bfloat16(v - __bfloat162float(h));
    }
}

__device__ __forceinline__ uint32_t smem_u32(const void* p) {
    uint32_t a;
    asm("{ .reg .u64 t; cvta.to.shared.u64 t, %1; cvt.u32.u64 %0, t; }"
        : "=r"(a) : "l"(p));
    return a;
}
__device__ __forceinline__ void split2(float a, float b, uint32_t& hi, uint32_t& lo) {
    __nv_bfloat16 ha = __float2bfloat16(a), hb = __float2bfloat16(b);
    __nv_bfloat16 la = __float2bfloat16(a - __bfloat162float(ha));
    __nv_bfloat16 lb = __float2bfloat16(b - __bfloat162float(hb));
    hi = (uint32_t)__bfloat16_as_ushort(ha) | ((uint32_t)__bfloat16_as_ushort(hb) << 16);
    lo = (uint32_t)__bfloat16_as_ushort(la) | ((uint32_t)__bfloat16_as_ushort(lb) << 16);
}
__device__ __forceinline__ float gelu_f(float v) {
    return 0.5f * v * (1.0f + erff(v * 0.70710678118654752f));
}
__device__ __forceinline__ float silu_f(float v) {
    return v / (1.f + expf(-v));
}

#define FMA2(d,a,b,c) asm("fma.rn.f32x2 %0, %1, %2, %3;" \
    : "=l"(d) : "l"(a), "l"(b), "l"(c))
#define MUL2(d,a,b) asm("mul.rn.f32x2 %0, %1, %2;" : "=l"(d) : "l"(a), "l"(b))
__device__ __forceinline__ u64t pack2(float lo, float hi) {
    u64t r;
    asm("mov.b64 %0, {%1,%2};" : "=l"(r) : "r"(__float_as_uint(lo)), "r"(__float_as_uint(hi)));
    return r;
}
__device__ __forceinline__ void unpack2(u64t v, float& lo, float& hi) {
    uint32_t a, b;
    asm("mov.b64 {%0,%1}, %2;" : "=r"(a), "=r"(b) : "l"(v));
    lo = __uint_as_float(a); hi = __uint_as_float(b);
}

#define LDSM4(r0,r1,r2,r3,addr) asm volatile( \
    "ldmatrix.sync.aligned.m8n8.x4.shared.b16 {%0,%1,%2,%3}, [%4];" \
    : "=r"(r0),"=r"(r1),"=r"(r2),"=r"(r3) : "r"(addr))

#define MMA16816(c,a0,a1,a2,a3,b0,b1) asm volatile( \
    "mma.sync.aligned.m16n8k16.row.col.f32.bf16.bf16.f32 " \
    "{%0,%1,%2,%3}, {%4,%5,%6,%7}, {%8,%9}, {%0,%1,%2,%3};" \
    : "+f"((c)[0]),"+f"((c)[1]),"+f"((c)[2]),"+f"((c)[3]) \
    : "r"(a0),"r"(a1),"r"(a2),"r"(a3),"r"(b0),"r"(b1))

// ---------- HMMA GEMM: bf16x3 split, 2-stage cp.async, 2 CTAs/SM ----------
// op0: Cf=v  op1: Cf+=v  op2: split(gelu(v))  op3: split(silu(Aux)*v)
// op4: Cf=rope(v) for cols<2048 (Cos/Sin), else v
#define ROWE 40
#define TILEB 10240u
#define STGB  40960u
#define MGSMEM 81920
__global__ void __launch_bounds__(256, 2) mma_gemm(
    const __nv_bfloat16* __restrict__ Ah, const __nv_bfloat16* __restrict__ Al,
    const __nv_bfloat16* __restrict__ Bh, const __nv_bfloat16* __restrict__ Bl,
    float* __restrict__ Cf, __nv_bfloat16* __restrict__ Chi,
    __nv_bfloat16* __restrict__ Clo, const float* __restrict__ Aux,
    const float* __restrict__ Cos, const float* __restrict__ Sin,
    int M, int N, int K, long long sA, long long sB, long long sC, int op)
{
    extern __shared__ char smraw[];
    Ah += (long long)blockIdx.z * sA;  Al += (long long)blockIdx.z * sA;
    Bh += (long long)blockIdx.z * sB;  Bl += (long long)blockIdx.z * sB;
    if (Cf)  Cf  += (long long)blockIdx.z * sC;
    if (Chi) { Chi += (long long)blockIdx.z * sC; Clo += (long long)blockIdx.z * sC; }
    if (Aux) Aux += (long long)blockIdx.z * sC;
    const int tid = threadIdx.x, lane = tid & 31, w = tid >> 5;
    const int warp_m = w & 3, warp_n = w >> 2;
    const int row0 = blockIdx.y << 7, col0 = blockIdx.x << 7;
    const uint32_t sb = smem_u32(smraw);

    const __nv_bfloat16* Ahg = Ah + (size_t)row0 * K;
    const __nv_bfloat16* Alg = Al + (size_t)row0 * K;
    const __nv_bfloat16* Bhg = Bh + (size_t)col0 * K;
    const __nv_bfloat16* Blg = Bl + (size_t)col0 * K;
    const int S = K >> 5;

    float acc[2][8][4];
#pragma unroll
    for (int mt = 0; mt < 2; mt++)
#pragma unroll
        for (int nt = 0; nt < 8; nt++)
#pragma unroll
            for (int j = 0; j < 4; j++) acc[mt][nt][j] = 0.f;

    auto issue = [&](int s) {
        if (s < S) {
            uint32_t base = sb + (uint32_t)(s & 1) * STGB;
            int k0e = s << 5;
            const __nv_bfloat16* gsrc[4] = {Ahg, Alg, Bhg, Blg};
#pragma unroll
            for (int t4 = 0; t4 < 4; t4++) {
                const __nv_bfloat16* gp = gsrc[t4] + k0e;
                uint32_t tb = base + (uint32_t)t4 * TILEB;
#pragma unroll
                for (int i = 0; i < 2; i++) {
                    int c = (i << 8) + tid, row = c >> 2, q = c & 3;
                    uint32_t d = tb + (uint32_t)(row * (ROWE*2) + q * 16);
                    const void* sp = (const char*)(gp + (size_t)row * K) + (q << 4);
                    asm volatile("cp.async.cg.shared.global [%0], [%1], 16;"
                                 :: "r"(d), "l"(sp));
                }
            }
        }
        asm volatile("cp.async.commit_group;" ::: "memory");
    };

    const uint32_t a_off = (uint32_t)((lane & 15) * ROWE + ((lane >> 4) << 3)) * 2u;
    const uint32_t b_off = (uint32_t)(((lane & 7) + ((lane >> 4) << 3)) * ROWE
                                      + (((lane >> 3) & 1) << 3)) * 2u;
    const uint32_t a_mrow = (uint32_t)(warp_m * 32) * (ROWE * 2u);
    const uint32_t b_nrow = (uint32_t)(warp_n * 64) * (ROWE * 2u);

    auto compute = [&](uint32_t base) {
#pragma unroll
        for (int k16 = 0; k16 < 2; k16++) {
            uint32_t kb = (uint32_t)(k16 << 5);
            uint32_t b[4][4];
            uint32_t ah[2][4], al[2][4];
#pragma unroll
            for (int ntp = 0; ntp < 4; ntp++) {
                uint32_t bd = base + 2u * TILEB + b_nrow
                              + (uint32_t)(ntp * 16) * (ROWE*2u) + b_off + kb;
                LDSM4(b[ntp][0], b[ntp][1], b[ntp][2], b[ntp][3], bd);
            }
#pragma unroll
            for (int mt = 0; mt < 2; mt++) {
                uint32_t ad = base + a_mrow + (uint32_t)(mt * 16) * (ROWE*2u)
                              + a_off + kb;
                LDSM4(ah[mt][0], ah[mt][1], ah[mt][2], ah[mt][3], ad);
                LDSM4(al[mt][0], al[mt][1], al[mt][2], al[mt][3], ad + TILEB);
            }
#pragma unroll
            for (int mt = 0; mt < 2; mt++)
#pragma unroll
                for (int nt = 0; nt < 8; nt++) {
                    int ntp = nt >> 1, hi = (nt & 1) << 1;
                    MMA16816(acc[mt][nt], ah[mt][0], ah[mt][1], ah[mt][2], ah[mt][3],
                             b[ntp][hi], b[ntp][hi + 1]);
                }
#pragma unroll
            for (int mt = 0; mt < 2; mt++)
#pragma unroll
                for (int nt = 0; nt < 8; nt++) {
                    int ntp = nt >> 1, hi = (nt & 1) << 1;
                    MMA16816(acc[mt][nt], al[mt][0], al[mt][1], al[mt][2], al[mt][3],
                             b[ntp][hi], b[ntp][hi + 1]);
                }
#pragma unroll
            for (int ntp = 0; ntp < 4; ntp++) {
                uint32_t bd = base + 3u * TILEB + b_nrow
                              + (uint32_t)(ntp * 16) * (ROWE*2u) + b_off + kb;
                LDSM4(b[ntp][0], b[ntp][1], b[ntp][2], b[ntp][3], bd);
            }
#pragma unroll
            for (int mt = 0; mt < 2; mt++)
#pragma unroll
                for (int nt = 0; nt < 8; nt++) {
                    int ntp = nt >> 1, hi = (nt & 1) << 1;
                    MMA16816(acc[mt][nt], ah[mt][0], ah[mt][1], ah[mt][2], ah[mt][3],
                             b[ntp][hi], b[ntp][hi + 1]);
                }
        }
    };

    issue(0);
    for (int s = 0; s < S; s++) {
        issue(s + 1);
        asm volatile("cp.async.wait_group 1;" ::: "memory");
        __syncthreads();
        compute(sb + (uint32_t)(s & 1) * STGB);
        __syncthreads();
    }

    const int rbase = row0 + warp_m * 32 + (lane >> 2);
    const int cbase = col0 + warp_n * 64 + ((lane & 3) << 1);
#pragma unroll
    for (int mt = 0; mt < 2; mt++) {
#pragma unroll
        for (int nt = 0; nt < 8; nt++) {
#pragma unroll
            for (int half = 0; half < 2; half++) {
                int r = rbase + mt * 16 + half * 8;
                int c = cbase + nt * 8;
                size_t idx = (size_t)r * N + c;
                float v0 = acc[mt][nt][half * 2], v1 = acc[mt][nt][half * 2 + 1];
                if (op == 0) {
                    *(float2*)(Cf + idx) = make_float2(v0, v1);
                } else if (op == 1) {
                    float2 old = *(const float2*)(Cf + idx);
                    *(float2*)(Cf + idx) = make_float2(v0 + old.x, v1 + old.y);
                } else if (op == 4) {
                    float o0 = v0, o1 = v1;
                    if (c < 2048) {
                        int n = r & (Nn - 1);
                        int i = (c & 63) >> 1;
                        float co = Cos[n * 32 + i], si = Sin[n * 32 + i];
                        o0 = v0 * co - v1 * si;
                        o1 = v0 * si + v1 * co;
                    }
                    *(float2*)(Cf + idx) = make_float2(o0, o1);
                } else {
                    float p0, p1;
                    if (op == 2) { p0 = gelu_f(v0); p1 = gelu_f(v1); }
                    else {
                        float2 a2 = *(const float2*)(Aux + idx);
                        p0 = silu_f(a2.x) * v0; p1 = silu_f(a2.y) * v1;
                    }
                    uint32_t h_, l_;
                    split2(p0, p1, h_, l_);
                    *(uint32_t*)(Chi + idx) = h_;
                    *(uint32_t*)(Clo + idx) = l_;
                }
            }
        }
    }
}

// silu(h1)*h3 from packed h13 [TOK, 5632] -> bf16 hi/lo [TOK, FFHn]
__global__ void silu_split_kernel(const float* __restrict__ h13,
                                  __nv_bfloat16* __restrict__ hh,
                                  __nv_bfloat16* __restrict__ hl)
{
    int idx = blockIdx.x * 256 + threadIdx.x;     // pair index
    int t = idx / (FFHn / 2);
    int j = (idx - t * (FFHn / 2)) * 2;
    const float* row = h13 + (size_t)t * (2 * FFHn);
    float2 a = *(const float2*)(row + j);
    float2 b = *(const float2*)(row + FFHn + j);
    float p0 = silu_f(a.x) * b.x, p1 = silu_f(a.y) * b.y;
    uint32_t h_, l_;
    split2(p0, p1, h_, l_);
    *(uint32_t*)(hh + (size_t)t * FFHn + j) = h_;
    *(uint32_t*)(hl + (size_t)t * FFHn + j) = l_;
}

__global__ void rmsnorm_kernel(const float* __restrict__ x, const float* __restrict__ w,
                               float* __restrict__ out, __nv_bfloat16* __restrict__ oh,
                               __nv_bfloat16* __restrict__ ol)
{
    __shared__ float red[256];
    int t = blockIdx.x;
    const float* xr = x + (size_t)t * Dn;
    float ss = 0.f;
    for (int i = threadIdx.x; i < Dn; i += 256) { float v = xr[i]; ss += v * v; }
    red[threadIdx.x] = ss; __syncthreads();
    for (int s = 128; s > 0; s >>= 1) {
        if (threadIdx.x < s) red[threadIdx.x] += red[threadIdx.x + s];
        __syncthreads();
    }
    float inv = rsqrtf(red[0] * (1.0f / Dn) + 1e-5f);
    float* orow = out + (size_t)t * Dn;
    __nv_bfloat16* ohr = oh + (size_t)t * Dn;
    __nv_bfloat16* olr = ol + (size_t)t * Dn;
    for (int i = threadIdx.x * 2; i < Dn; i += 512) {
        float a = xr[i] * inv * w[i], b = xr[i+1] * inv * w[i+1];
        orow[i] = a; orow[i+1] = b;
        uint32_t h_, l_;
        split2(a, b, h_, l_);
        *(uint32_t*)(ohr + i) = h_;
        *(uint32_t*)(olr + i) = l_;
    }
}

#define FST 72
__global__ void __launch_bounds__(256) flash_kernel(const float* __restrict__ qkv,
                                                    __nv_bfloat16* __restrict__ outh,
                                                    __nv_bfloat16* __restrict__ outl)
{
    extern __shared__ float sm[];
    float* Qs = sm;
    float* Ks = Qs + 64 * FST;
    float* Vs = Ks + 64 * FST;
    float* Ps = Vs + 64 * FST;
    const int qt = blockIdx.x;
    const int bh = blockIdx.y;
    const int b = bh >> 4, h = bh & 15;
    const int tid = threadIdx.x;
    const int r = tid >> 2, g = tid & 3;
    const size_t base = (size_t)b * Nn * (3 * Dn) + h * HDn;
    const int q0 = qt * 64;

    for (int i = tid; i < 64 * 64; i += 256) {
        int rr = i >> 6, cc = i & 63;
        Qs[rr * FST + cc] = qkv[base + (size_t)(q0 + rr) * (3 * Dn) + cc];
    }
    u64t o2[8];
#pragma unroll
    for (int i = 0; i < 8; i++) o2[i] = 0ULL;
    float m = -1e30f, l = 0.f;

    for (int kt = 0; kt <= qt; kt++) {
        __syncthreads();
        int k0 = kt * 64;
        for (int i = tid; i < 64 * 64; i += 256) {
            int rr = i >> 6, cc = i & 63;
            size_t off = base + (size_t)(k0 + rr) * (3 * Dn) + cc;
            Ks[rr * FST + cc] = qkv[off + Dn];
            Vs[rr * FST + cc] = qkv[off + 2 * Dn];
        }
        __syncthreads();
        float s[16];
        const u64t* Q2 = (const u64t*)(Qs + r * FST);
#pragma unroll
        for (int jj = 0; jj < 16; jj++) {
            int j = g * 16 + jj;
            const u64t* K2 = (const u64t*)(Ks + j * FST);
            u64t acc2 = 0ULL;
#pragma unroll
            for (int d2 = 0; d2 < 32; d2++)
                FMA2(acc2, Q2[d2], K2[d2], acc2);
            float alo, ahi;
            unpack2(acc2, alo, ahi);
            float a = alo + ahi;
            s[jj] = (k0 + j <= q0 + r) ? a * 0.125f : -1e30f;
        }
        float mloc = s[0];
#pragma unroll
        for (int jj = 1; jj < 16; jj++) mloc = fmaxf(mloc, s[jj]);
        mloc = fmaxf(mloc, __shfl_xor_sync(0xffffffffu, mloc, 1));
        mloc = fmaxf(mloc, __shfl_xor_sync(0xffffffffu, mloc, 2));
        float mnew = fmaxf(m, mloc);
        float corr = expf(m - mnew);
        float psum = 0.f;
#pragma unroll
        for (int jj = 0; jj < 16; jj++) { s[jj] = expf(s[jj] - mnew); psum += s[jj]; }
        psum += __shfl_xor_sync(0xffffffffu, psum, 1);
        psum += __shfl_xor_sync(0xffffffffu, psum, 2);
        l = l * corr + psum;
        m = mnew;
        u64t corr2 = pack2(corr, corr);
#pragma unroll
        for (int i = 0; i < 8; i++) MUL2(o2[i], o2[i], corr2);
        float* Pr = Ps + r * FST + g * 16;
#pragma unroll
        for (int jj = 0; jj < 16; jj++) Pr[jj] = s[jj];
        __syncwarp();
#pragma unroll 4
        for (int k = 0; k < 64; k++) {
            float pv = Ps[r * FST + k];
            u64t pv2 = pack2(pv, pv);
            const u64t* V2 = (const u64t*)(Vs + k * FST + g * 16);
#pragma unroll
            for (int i = 0; i < 8; i++)
                FMA2(o2[i], pv2, V2[i], o2[i]);
        }
    }
    float invl = 1.f / l;
    float o[16];
#pragma unroll
    for (int i = 0; i < 8; i++) {
        float lo, hi;
        unpack2(o2[i], lo, hi);
        o[2*i] = lo * invl; o[2*i+1] = hi * invl;
    }
    size_t ob = ((size_t)(b * Nn + q0 + r)) * Dn + h * HDn + g * 16;
    uint32_t hh[8], ll[8];
#pragma unroll
    for (int j = 0; j < 8; j++)
        split2(o[2*j], o[2*j+1], hh[j], ll[j]);
    *(uint4*)(outh + ob)     = make_uint4(hh[0], hh[1], hh[2], hh[3]);
    *(uint4*)(outh + ob + 8) = make_uint4(hh[4], hh[5], hh[6], hh[7]);
    *(uint4*)(outl + ob)     = make_uint4(ll[0], ll[1], ll[2], ll[3]);
    *(uint4*)(outl + ob + 8) = make_uint4(ll[4], ll[5], ll[6], ll[7]);
}

__global__ void gate_kernel(const float* __restrict__ xn, const float* __restrict__ wg,
                            float* __restrict__ raw, int* __restrict__ idx1,
                            int* __restrict__ idx2, int* __restrict__ keep,
                            float* __restrict__ g1o, float* __restrict__ g2o,
                            unsigned key0, unsigned key1)
{
    __shared__ float red[8 * 256];
    int t = blockIdx.x;
    const float* xr = xn + (size_t)t * Dn;
    float acc[8] = {0,0,0,0,0,0,0,0};
    for (int i = threadIdx.x; i < Dn; i += 256) {
        float v = xr[i];
        const float* wr = wg + (size_t)i * NEn;
#pragma unroll
        for (int e = 0; e < 8; e++) acc[e] += v * wr[e];
    }
#pragma unroll
    for (int e = 0; e < 8; e++) red[e * 256 + threadIdx.x] = acc[e];
    __syncthreads();
    for (int s = 128; s > 0; s >>= 1) {
        if (threadIdx.x < s) {
#pragma unroll
            for (int e = 0; e < 8; e++)
                red[e * 256 + threadIdx.x] += red[e * 256 + threadIdx.x + s];
        }
        __syncthreads();
    }
    if (threadIdx.x == 0) {
        float p[8];
        float mx = red[0];
#pragma unroll
        for (int e = 1; e < 8; e++) mx = fmaxf(mx, red[e * 256]);
        float sum = 0.f;
#pragma unroll
        for (int e = 0; e < 8; e++) { p[e] = expf(red[e * 256] - mx); sum += p[e]; }
#pragma unroll
        for (int e = 0; e < 8; e++) p[e] /= sum;
        int i1 = 0; float b1 = p[0];
#pragma unroll
        for (int e = 1; e < 8; e++) if (p[e] > b1) { b1 = p[e]; i1 = e; }
        int i2 = -1; float b2 = -1.f;
#pragma unroll
        for (int e = 0; e < 8; e++) if (e != i1 && p[e] > b2) { b2 = p[e]; i2 = e; }
        float denom = b1 + b2 + 1e-9f;
        float g1 = b1 / denom, g2 = b2 / denom;
        unsigned x0 = 0u, x1 = (unsigned)t;
        threefry2x32(key0, key1, x0, x1);
        unsigned bits = x0 ^ x1;
        float u = __uint_as_float((bits >> 9) | 0x3F800000u) - 1.0f;
        int kp = (u < (g2 / 0.2f)) ? 1 : 0;
#pragma unroll
        for (int e = 0; e < 8; e++) raw[t * NEn + e] = p[e];
        idx1[t] = i1; idx2[t] = i2; keep[t] = kp; g1o[t] = g1; g2o[t] = g2;
    }
}

__global__ void loss_sum_kernel(const float* __restrict__ raw, const int* __restrict__ idx1,
                                float* __restrict__ rawsum, float* __restrict__ cnt1)
{
    __shared__ float r1[256], r2[256];
    int be = blockIdx.x, b = be >> 3, e = be & 7;
    float s1 = 0.f, s2 = 0.f;
    for (int n = threadIdx.x; n < Nn; n += 256) {
        int t = b * Nn + n;
        s1 += raw[t * NEn + e];
        s2 += (idx1[t] == e) ? 1.f : 0.f;
    }
    r1[threadIdx.x] = s1; r2[threadIdx.x] = s2; __syncthreads();
    for (int s = 128; s > 0; s >>= 1) {
        if (threadIdx.x < s) {
            r1[threadIdx.x] += r1[threadIdx.x + s];
            r2[threadIdx.x] += r2[threadIdx.x + s];
        }
        __syncthreads();
    }
    if (threadIdx.x == 0) { rawsum[be] = r1[0]; cnt1[be] = r2[0]; }
}

__global__ void slots_kernel(const int* __restrict__ idx1, const int* __restrict__ idx2,
                             const int* __restrict__ keep, int* __restrict__ slot1,
                             int* __restrict__ slot2, const float* __restrict__ rawsum,
                             const float* __restrict__ cnt1, float* __restrict__ loss_out)
{
    __shared__ char si1[TOK], si2[TOK], skp[TOK];
    __shared__ float lred[32];
    int tid = threadIdx.x;
    for (int i = tid; i < TOK; i += 256) {
        si1[i] = (char)idx1[i]; si2[i] = (char)idx2[i]; skp[i] = (char)keep[i];
        slot1[i] = -1; slot2[i] = -1;
    }
    __syncthreads();
    if (tid < 32) {
        int b = tid >> 3, e = tid & 7;
        int base = (e * Bn + b) * CAPn;
        int c = 0;
        for (int n = 0; n < Nn; n++) {
            int t = b * Nn + n;
            if (si1[t] == e) { if (c < CAPn) slot1[t] = base + c; c++; }
        }
        int m1c = c < CAPn ? c : CAPn;
        int c2 = 0;
        for (int n = 0; n < Nn; n++) {
            int t = b * Nn + n;
            if (si2[t] == e && skp[t]) {
                int pos = m1c + c2; c2++;
                if (pos < CAPn) slot2[t] = base + pos;
            }
        }
        lred[tid] = rawsum[tid] * (1.f / Nn) * cnt1[tid] * (1.f / Nn);
    }
    __syncthreads();
    if (tid == 0) {
        float s = 0.f;
        for (int i = 0; i < 32; i++) s += lred[i];
        *loss_out += s * 0.02f;
    }
}

__global__ void scatter_kernel(const __nv_bfloat16* __restrict__ xnh,
                               const __nv_bfloat16* __restrict__ xnl,
                               const int* __restrict__ slot1, const int* __restrict__ slot2,
                               __nv_bfloat16* __restrict__ xeh, __nv_bfloat16* __restrict__ xel)
{
    int t = blockIdx.x;
    int s1 = slot1[t], s2 = slot2[t];
    if (s1 < 0 && s2 < 0) return;
    uint4 vh = ((const uint4*)(xnh + (size_t)t * Dn))[threadIdx.x];
    uint4 vl = ((const uint4*)(xnl + (size_t)t * Dn))[threadIdx.x];
    if (s1 >= 0) {
        ((uint4*)(xeh + (size_t)s1 * Dn))[threadIdx.x] = vh;
        ((uint4*)(xel + (size_t)s1 * Dn))[threadIdx.x] = vl;
    }
    if (s2 >= 0) {
        ((uint4*)(xeh + (size_t)s2 * Dn))[threadIdx.x] = vh;
        ((uint4*)(xel + (size_t)s2 * Dn))[threadIdx.x] = vl;
    }
}

__global__ void combine_kernel(const float* __restrict__ ye, const int* __restrict__ slot1,
                               const int* __restrict__ slot2, const float* __restrict__ g1,
                               const float* __restrict__ g2, float* __restrict__ x)
{
    int t = blockIdx.x;
    int s1 = slot1[t], s2 = slot2[t];
    if (s1 < 0 && s2 < 0) return;
    float a = (s1 >= 0) ? g1[t] : 0.f;
    float b = (s2 >= 0) ? g2[t] : 0.f;
    float4* xr = (float4*)(x + (size_t)t * Dn);
    float4 v = xr[threadIdx.x];
    if (s1 >= 0) {
        float4 w = ((const float4*)(ye + (size_t)s1 * Dn))[threadIdx.x];
        v.x += a * w.x; v.y += a * w.y; v.z += a * w.z; v.w += a * w.w;
    }
    if (s2 >= 0) {
        float4 w = ((const float4*)(ye + (size_t)s2 * Dn))[threadIdx.x];
        v.x += b * w.x; v.y += b * w.y; v.z += b * w.z; v.w += b * w.w;
    }
    xr[threadIdx.x] = v;
}

extern "C" void kernel_launch(void* const* d_in, const int* in_sizes, int n_in,
                              void* d_out, int out_size)
{
    const float* x    = (const float*)d_in[0];
    const float* cosb = (const float*)d_in[1];
    const float* sinb = (const float*)d_in[2];
    const float* ln   = (const float*)d_in[3];
    const float* wqkv = (const float*)d_in[4];
    const float* wo   = (const float*)d_in[5];
    const float* w1   = (const float*)d_in[6];
    const float* w2   = (const float*)d_in[7];
    const float* w3   = (const float*)d_in[8];
    const float* wg   = (const float*)d_in[9];
    const float* mw1  = (const float*)d_in[10];
    const float* mw2  = (const float*)d_in[11];
    float* xout = (float*)d_out;

    void* p;
    cudaGetSymbolAddress(&p, g_norm);  float* norm  = (float*)p;
    cudaGetSymbolAddress(&p, g_normh); __nv_bfloat16* normh = (__nv_bfloat16*)p;
    cudaGetSymbolAddress(&p, g_norml); __nv_bfloat16* norml = (__nv_bfloat16*)p;
    cudaGetSymbolAddress(&p, g_big);   float* big   = (float*)p;
    cudaGetSymbolAddress(&p, g_attnh); __nv_bfloat16* attnh = (__nv_bfloat16*)p;
    cudaGetSymbolAddress(&p, g_attnl); __nv_bfloat16* attnl = (__nv_bfloat16*)p;
    cudaGetSymbolAddress(&p, g_h13);   float* h13   = (float*)p;
    cudaGetSymbolAddress(&p, g_hidh);  __nv_bfloat16* hidh = (__nv_bfloat16*)p;
    cudaGetSymbolAddress(&p, g_hidl);  __nv_bfloat16* hidl = (__nv_bfloat16*)p;
    cudaGetSymbolAddress(&p, g_xeh);   __nv_bfloat16* xeh = (__nv_bfloat16*)p;
    cudaGetSymbolAddress(&p, g_xel);   __nv_bfloat16* xel = (__nv_bfloat16*)p;
    cudaGetSymbolAddress(&p, g_ye);    float* ye    = (float*)p;
    cudaGetSymbolAddress(&p, g_raw);   float* raw   = (float*)p;
    cudaGetSymbolAddress(&p, g_idx1);  int* idx1    = (int*)p;
    cudaGetSymbolAddress(&p, g_idx2);  int* idx2    = (int*)p;
    cudaGetSymbolAddress(&p, g_keep);  int* keep    = (int*)p;
    cudaGetSymbolAddress(&p, g_slot1); int* slot1   = (int*)p;
    cudaGetSymbolAddress(&p, g_slot2); int* slot2   = (int*)p;
    cudaGetSymbolAddress(&p, g_g1);    float* g1    = (float*)p;
    cudaGetSymbolAddress(&p, g_g2);    float* g2    = (float*)p;
    cudaGetSymbolAddress(&p, g_rawsum);float* rawsum= (float*)p;
    cudaGetSymbolAddress(&p, g_cnt1);  float* cnt1  = (float*)p;
    cudaGetSymbolAddress(&p, g_lossbuf); float* lossbuf = (float*)p;
    cudaGetSymbolAddress(&p, g_whi);   __nv_bfloat16* whi = (__nv_bfloat16*)p;
    cudaGetSymbolAddress(&p, g_wlo);   __nv_bfloat16* wlo = (__nv_bfloat16*)p;

    cudaFuncSetAttribute(flash_kernel, cudaFuncAttributeMaxDynamicSharedMemorySize, 73728);
    cudaFuncSetAttribute(mma_gemm, cudaFuncAttributeMaxDynamicSharedMemorySize, MGSMEM);

    float* lossp = (out_size > TOK * Dn) ? (xout + (size_t)TOK * Dn) : lossbuf;

    unsigned k1a, k1b, k2a, k2b;
    { unsigned a = 0u, b = 0u; threefry2x32(0u, 42u, a, b); k1a = a; k1b = b; }
    { unsigned a = 0u, b = 1u; threefry2x32(0u, 42u, a, b); k2a = a; k2b = b; }

    const long long sXE  = (long long)Bn * CAPn * Dn;
    const long long sHID = (long long)Bn * CAPn * MOEHn;
    dim3 wb(32, 8);
#define NILB (__nv_bfloat16*)0
#define NILF (const float*)0

    // item order for ncu -s 5 -c 1:
    // 0 memcpy, 1 wprep(qkv), 2 rmsnorm, 3 qkv gemm(op4), 4 memset, 5 flash <- profiled
    cudaMemcpyAsync(xout, x, (size_t)TOK * Dn * sizeof(float),
                    cudaMemcpyDeviceToDevice, 0);
    wprep_kernel<<<dim3(96, 32, 3),  wb>>>(wqkv, whi + QKV_OFF, wlo + QKV_OFF,
                                           1024, 3072, 1024LL*3072, 1024LL*3072);
    rmsnorm_kernel<<<TOK, 256>>>(xout, ln, norm, normh, norml);
    mma_gemm<<<dim3(24, 32, 1), 256, MGSMEM>>>(
        normh, norml, whi + QKV_OFF, wlo + QKV_OFF,
        big, NILB, NILB, NILF, cosb, sinb, TOK, 3072, 1024, 0, 0, 0, 4);
    cudaMemsetAsync(lossp, 0, sizeof(float), 0);
    flash_kernel<<<dim3(Nn / 64, Bn * NHn), 256, 73728>>>(big, attnh, attnl);

    wprep_kernel<<<dim3(32, 32, 3),  wb>>>(wo,  whi + WO_OFF,  wlo + WO_OFF,
                                           1024, 1024, 1024LL*1024, 1024LL*1024);
    wprep_kernel<<<dim3(88, 32, 3),  wb>>>(w1,  whi + W13_OFF, wlo + W13_OFF,
                                           1024, 2816, 2883584LL, W13_STR);
    wprep_kernel<<<dim3(88, 32, 3),  wb>>>(w3,  whi + W13_OFF + 2883584LL,
                                           wlo + W13_OFF + 2883584LL,
                                           1024, 2816, 2883584LL, W13_STR);
    wprep_kernel<<<dim3(32, 88, 3),  wb>>>(w2,  whi + W2_OFF,  wlo + W2_OFF,
                                           2816, 1024, 2816LL*1024, 2816LL*1024);
    wprep_kernel<<<dim3(64, 32, 16), wb>>>(mw1, whi + MW1_OFF, wlo + MW1_OFF,
                                           1024, 2048, 1024LL*2048, 1024LL*2048);
    wprep_kernel<<<dim3(32, 64, 16), wb>>>(mw2, whi + MW2_OFF, wlo + MW2_OFF,
                                           2048, 1024, 2048LL*1024, 2048LL*1024);

    auto attn_tail = [&](int la) {
        mma_gemm<<<dim3(8, 32, 1), 256, MGSMEM>>>(
            attnh, attnl,
            whi + WO_OFF + (long long)la * 1048576,
            wlo + WO_OFF + (long long)la * 1048576,
            xout, NILB, NILB, NILF, NILF, NILF, TOK, 1024, 1024, 0, 0, 0, 1);
    };
    auto attn_layer = [&](int la, int lnidx) {
        rmsnorm_kernel<<<TOK, 256>>>(xout, ln + (size_t)lnidx * Dn, norm, normh, norml);
        mma_gemm<<<dim3(24, 32, 1), 256, MGSMEM>>>(
            normh, norml,
            whi + QKV_OFF + (long long)la * 3145728,
            wlo + QKV_OFF + (long long)la * 3145728,
            big, NILB, NILB, NILF, cosb, sinb, TOK, 3072, 1024, 0, 0, 0, 4);
        flash_kernel<<<dim3(Nn / 64, Bn * NHn), 256, 73728>>>(big, attnh, attnl);
        attn_tail(la);
    };
    auto mlp_layer = [&](int lm, int lnidx) {
        rmsnorm_kernel<<<TOK, 256>>>(xout, ln + (size_t)lnidx * Dn, norm, normh, norml);
        mma_gemm<<<dim3(44, 32, 1), 256, MGSMEM>>>(
            normh, norml,
            whi + W13_OFF + (long long)lm * W13_STR,
            wlo + W13_OFF + (long long)lm * W13_STR,
            h13, NILB, NILB, NILF, NILF, NILF, TOK, 5632, 1024, 0, 0, 0, 0);
        silu_split_kernel<<<TOK * (FFHn / 2) / 256, 256>>>(h13, hidh, hidl);
        mma_gemm<<<dim3(8, 32, 1), 256, MGSMEM>>>(
            hidh, hidl,
            whi + W2_OFF + (long long)lm * 2883584,
            wlo + W2_OFF + (long long)lm * 2883584,
            xout, NILB, NILB, NILF, NILF, NILF, TOK, 1024, 2816, 0, 0, 0, 1);
    };
    auto moe_layer = [&](int lo, int lnidx, unsigned ka, unsigned kbb) {
        rmsnorm_kernel<<<TOK, 256>>>(xout, ln + (size_t)lnidx * Dn, norm, normh, norml);
        gate_kernel<<<TOK, 256>>>(norm, wg + (size_t)lo * Dn * NEn,
                                  raw, idx1, idx2, keep, g1, g2, ka, kbb);
        loss_sum_kernel<<<Bn * NEn, 256>>>(raw, idx1, rawsum, cnt1);
        slots_kernel<<<1, 256>>>(idx1, idx2, keep, slot1, slot2, rawsum, cnt1, lossp);
        scatter_kernel<<<TOK, 128>>>(normh, norml, slot1, slot2, xeh, xel);
        mma_gemm<<<dim3(16, 5, 8), 256, MGSMEM>>>(
            xeh, xel,
            whi + MW1_OFF + (long long)lo * 16777216,
            wlo + MW1_OFF + (long long)lo * 16777216,
            (float*)0, hidh, hidl, NILF, NILF, NILF,
            Bn * CAPn, MOEHn, 1024, sXE, 2097152LL, sHID, 2);
        mma_gemm<<<dim3(8, 5, 8), 256, MGSMEM>>>(
            hidh, hidl,
            whi + MW2_OFF + (long long)lo * 16777216,
            wlo + MW2_OFF + (long long)lo * 16777216,
            ye, NILB, NILB, NILF, NILF, NILF,
            Bn * CAPn, 1024, 2048, sHID, 2097152LL, sXE, 0);
        combine_kernel<<<TOK, 256>>>(ye, slot1, slot2, g1, g2, xout);
    };

    attn_tail(0);               // layer-0 rmsnorm/qkv/flash issued above
    mlp_layer(0, 1);
    moe_layer(0, 2, k1a, k1b);
    mlp_layer(1, 3);
    attn_layer(1, 4);
    moe_layer(1, 5, k2a, k2b);
    attn_layer(2, 6);
    mlp_layer(2, 7);
}

// round 13
// speedup vs baseline: 1.9930x; 1.9930x over previous
#include <cuda_runtime.h>
#include <cuda_bf16.h>
#include <stdint.h>
#include <math.h>

#define Bn 4
#define Nn 1024
#define Dn 1024
#define NHn 16
#define HDn 64
#define FFHn 2816
#define MOEHn 2048
#define NEn 8
#define CAPn 160
#define TOK (Bn*Nn)
#define NSLOT (NEn*Bn*CAPn)

#define QKV_OFF 0LL
#define WO_OFF  9437184LL
#define W1_OFF  12582912LL
#define W3_OFF  21233664LL
#define W2_OFF  29884416LL
#define MW1_OFF 38535168LL
#define MW2_OFF 72089600LL
#define WTOTAL  105644032LL

typedef unsigned long long u64t;

static __device__ float g_norm[TOK*Dn];
static __device__ __nv_bfloat16 g_normh[TOK*Dn], g_norml[TOK*Dn];
static __device__ float g_big [TOK*3*Dn];
static __device__ __nv_bfloat16 g_attnh[TOK*Dn], g_attnl[TOK*Dn];
static __device__ float g_h1[TOK*FFHn];
static __device__ __nv_bfloat16 g_hidh[TOK*FFHn], g_hidl[TOK*FFHn];
static __device__ __nv_bfloat16 g_xeh[NSLOT*Dn], g_xel[NSLOT*Dn];
static __device__ float g_ye[NSLOT*Dn];
static __device__ float g_raw [TOK*NEn];
static __device__ int   g_idx1[TOK], g_idx2[TOK], g_keep[TOK];
static __device__ int   g_slot1[TOK], g_slot2[TOK];
static __device__ float g_g1[TOK], g_g2[TOK];
static __device__ float g_rawsum[Bn*NEn], g_cnt1[Bn*NEn];
static __device__ float g_lossbuf[1];
static __device__ __nv_bfloat16 g_whi[WTOTAL];
static __device__ __nv_bfloat16 g_wlo[WTOTAL];

__host__ __device__ __forceinline__ void threefry2x32(unsigned k0, unsigned k1,
                                                      unsigned& x0, unsigned& x1)
{
    unsigned ks2 = k0 ^ k1 ^ 0x1BD11BDAu;
    x0 += k0; x1 += k1;
#define TFR(r) { x0 += x1; x1 = (x1<<(r))|(x1>>(32-(r))); x1 ^= x0; }
    TFR(13) TFR(15) TFR(26) TFR(6)
    x0 += k1;  x1 += ks2 + 1u;
    TFR(17) TFR(29) TFR(16) TFR(24)
    x0 += ks2; x1 += k0 + 2u;
    TFR(13) TFR(15) TFR(26) TFR(6)
    x0 += k0;  x1 += k1 + 3u;
    TFR(17) TFR(29) TFR(16) TFR(24)
    x0 += k1;  x1 += ks2 + 4u;
    TFR(13) TFR(15) TFR(26) TFR(6)
    x0 += ks2; x1 += k0 + 5u;
#undef TFR
}

__global__ void wprep_kernel(const float* __restrict__ W, __nv_bfloat16* __restrict__ hi,
                             __nv_bfloat16* __restrict__ lo, int K, int N,
                             long long sW, long long sO)
{
    __shared__ float t[32][33];
    W  += (long long)blockIdx.z * sW;
    hi += (long long)blockIdx.z * sO;
    lo += (long long)blockIdx.z * sO;
    int n0 = blockIdx.x * 32, k0 = blockIdx.y * 32;
#pragma unroll
    for (int j = 0; j < 4; j++)
        t[threadIdx.y + j*8][threadIdx.x] =
            W[(size_t)(k0 + threadIdx.y + j*8) * N + n0 + threadIdx.x];
    __syncthreads();
#pragma unroll
    for (int j = 0; j < 4; j++) {
        int n = n0 + threadIdx.y + j*8, k = k0 + threadIdx.x;
        float v = t[threadIdx.x][threadIdx.y + j*8];
        __nv_bfloat16 h = __float2bfloat16(v);
        hi[(size_t)n * K + k] = h;
        lo[(size_t)n * K + k] = __float2bfloat16(v - __bfloat162float(h));
    }
}

__device__ __forceinline__ uint32_t smem_u32(const void* p) {
    uint32_t a;
    asm("{ .reg .u64 t; cvta.to.shared.u64 t, %1; cvt.u32.u64 %0, t; }"
        : "=r"(a) : "l"(p));
    return a;
}
__device__ __forceinline__ void split2(float a, float b, uint32_t& hi, uint32_t& lo) {
    __nv_bfloat16 ha = __float2bfloat16(a), hb = __float2bfloat16(b);
    __nv_bfloat16 la = __float2bfloat16(a - __bfloat162float(ha));
    __nv_bfloat16 lb = __float2bfloat16(b - __bfloat162float(hb));
    hi = (uint32_t)__bfloat16_as_ushort(ha) | ((uint32_t)__bfloat16_as_ushort(hb) << 16);
    lo = (uint32_t)__bfloat16_as_ushort(la) | ((uint32_t)__bfloat16_as_ushort(lb) << 16);
}
__device__ __forceinline__ float gelu_f(float v) {
    return 0.5f * v * (1.0f + erff(v * 0.70710678118654752f));
}
__device__ __forceinline__ float silu_f(float v) {
    return v / (1.f + expf(-v));
}

#define LDSM4(r0,r1,r2,r3,addr) asm volatile( \
    "ldmatrix.sync.aligned.m8n8.x4.shared.b16 {%0,%1,%2,%3}, [%4];" \
    : "=r"(r0),"=r"(r1),"=r"(r2),"=r"(r3) : "r"(addr))

#define MMA16816(c,a0,a1,a2,a3,b0,b1) asm volatile( \
    "mma.sync.aligned.m16n8k16.row.col.f32.bf16.bf16.f32 " \
    "{%0,%1,%2,%3}, {%4,%5,%6,%7}, {%8,%9}, {%0,%1,%2,%3};" \
    : "+f"((c)[0]),"+f"((c)[1]),"+f"((c)[2]),"+f"((c)[3]) \
    : "r"(a0),"r"(a1),"r"(a2),"r"(a3),"r"(b0),"r"(b1))

// ---------- HMMA GEMM: bf16x3 split, 2-stage cp.async, 2 CTAs/SM ----------
// op0: Cf=v  op1: Cf+=v  op2: split(gelu(v))  op3: split(silu(Aux)*v)  op4: rope
#define ROWE 40
#define TILEB 10240u
#define STGB  40960u
#define MGSMEM 81920
__global__ void __launch_bounds__(256, 2) mma_gemm(
    const __nv_bfloat16* __restrict__ Ah, const __nv_bfloat16* __restrict__ Al,
    const __nv_bfloat16* __restrict__ Bh, const __nv_bfloat16* __restrict__ Bl,
    float* __restrict__ Cf, __nv_bfloat16* __restrict__ Chi,
    __nv_bfloat16* __restrict__ Clo, const float* __restrict__ Aux,
    const float* __restrict__ Cos, const float* __restrict__ Sin,
    int M, int N, int K, long long sA, long long sB, long long sC, int op)
{
    extern __shared__ char smraw[];
    Ah += (long long)blockIdx.z * sA;  Al += (long long)blockIdx.z * sA;
    Bh += (long long)blockIdx.z * sB;  Bl += (long long)blockIdx.z * sB;
    if (Cf)  Cf  += (long long)blockIdx.z * sC;
    if (Chi) { Chi += (long long)blockIdx.z * sC; Clo += (long long)blockIdx.z * sC; }
    if (Aux) Aux += (long long)blockIdx.z * sC;
    const int tid = threadIdx.x, lane = tid & 31, w = tid >> 5;
    const int warp_m = w & 3, warp_n = w >> 2;
    const int row0 = blockIdx.y << 7, col0 = blockIdx.x << 7;
    const uint32_t sb = smem_u32(smraw);

    const __nv_bfloat16* Ahg = Ah + (size_t)row0 * K;
    const __nv_bfloat16* Alg = Al + (size_t)row0 * K;
    const __nv_bfloat16* Bhg = Bh + (size_t)col0 * K;
    const __nv_bfloat16* Blg = Bl + (size_t)col0 * K;
    const int S = K >> 5;

    float acc[2][8][4];
#pragma unroll
    for (int mt = 0; mt < 2; mt++)
#pragma unroll
        for (int nt = 0; nt < 8; nt++)
#pragma unroll
            for (int j = 0; j < 4; j++) acc[mt][nt][j] = 0.f;

    auto issue = [&](int s) {
        if (s < S) {
            uint32_t base = sb + (uint32_t)(s & 1) * STGB;
            int k0e = s << 5;
            const __nv_bfloat16* gsrc[4] = {Ahg, Alg, Bhg, Blg};
#pragma unroll
            for (int t4 = 0; t4 < 4; t4++) {
                const __nv_bfloat16* gp = gsrc[t4] + k0e;
                uint32_t tb = base + (uint32_t)t4 * TILEB;
#pragma unroll
                for (int i = 0; i < 2; i++) {
                    int c = (i << 8) + tid, row = c >> 2, q = c & 3;
                    uint32_t d = tb + (uint32_t)(row * (ROWE*2) + q * 16);
                    const void* sp = (const char*)(gp + (size_t)row * K) + (q << 4);
                    asm volatile("cp.async.cg.shared.global [%0], [%1], 16;"
                                 :: "r"(d), "l"(sp));
                }
            }
        }
        asm volatile("cp.async.commit_group;" ::: "memory");
    };

    const uint32_t a_off = (uint32_t)((lane & 15) * ROWE + ((lane >> 4) << 3)) * 2u;
    const uint32_t b_off = (uint32_t)(((lane & 7) + ((lane >> 4) << 3)) * ROWE
                                      + (((lane >> 3) & 1) << 3)) * 2u;
    const uint32_t a_mrow = (uint32_t)(warp_m * 32) * (ROWE * 2u);
    const uint32_t b_nrow = (uint32_t)(warp_n * 64) * (ROWE * 2u);

    auto compute = [&](uint32_t base) {
#pragma unroll
        for (int k16 = 0; k16 < 2; k16++) {
            uint32_t kb = (uint32_t)(k16 << 5);
            uint32_t b[4][4];
            uint32_t ah[2][4], al[2][4];
#pragma unroll
            for (int ntp = 0; ntp < 4; ntp++) {
                uint32_t bd = base + 2u * TILEB + b_nrow
                              + (uint32_t)(ntp * 16) * (ROWE*2u) + b_off + kb;
                LDSM4(b[ntp][0], b[ntp][1], b[ntp][2], b[ntp][3], bd);
            }
#pragma unroll
            for (int mt = 0; mt < 2; mt++) {
                uint32_t ad = base + a_mrow + (uint32_t)(mt * 16) * (ROWE*2u)
                              + a_off + kb;
                LDSM4(ah[mt][0], ah[mt][1], ah[mt][2], ah[mt][3], ad);
                LDSM4(al[mt][0], al[mt][1], al[mt][2], al[mt][3], ad + TILEB);
            }
#pragma unroll
            for (int mt = 0; mt < 2; mt++)
#pragma unroll
                for (int nt = 0; nt < 8; nt++) {
                    int ntp = nt >> 1, hi = (nt & 1) << 1;
                    MMA16816(acc[mt][nt], ah[mt][0], ah[mt][1], ah[mt][2], ah[mt][3],
                             b[ntp][hi], b[ntp][hi + 1]);
                }
#pragma unroll
            for (int mt = 0; mt < 2; mt++)
#pragma unroll
                for (int nt = 0; nt < 8; nt++) {
                    int ntp = nt >> 1, hi = (nt & 1) << 1;
                    MMA16816(acc[mt][nt], al[mt][0], al[mt][1], al[mt][2], al[mt][3],
                             b[ntp][hi], b[ntp][hi + 1]);
                }
#pragma unroll
            for (int ntp = 0; ntp < 4; ntp++) {
                uint32_t bd = base + 3u * TILEB + b_nrow
                              + (uint32_t)(ntp * 16) * (ROWE*2u) + b_off + kb;
                LDSM4(b[ntp][0], b[ntp][1], b[ntp][2], b[ntp][3], bd);
            }
#pragma unroll
            for (int mt = 0; mt < 2; mt++)
#pragma unroll
                for (int nt = 0; nt < 8; nt++) {
                    int ntp = nt >> 1, hi = (nt & 1) << 1;
                    MMA16816(acc[mt][nt], ah[mt][0], ah[mt][1], ah[mt][2], ah[mt][3],
                             b[ntp][hi], b[ntp][hi + 1]);
                }
        }
    };

    issue(0);
    for (int s = 0; s < S; s++) {
        issue(s + 1);
        asm volatile("cp.async.wait_group 1;" ::: "memory");
        __syncthreads();
        compute(sb + (uint32_t)(s & 1) * STGB);
        __syncthreads();
    }

    const int rbase = row0 + warp_m * 32 + (lane >> 2);
    const int cbase = col0 + warp_n * 64 + ((lane & 3) << 1);
#pragma unroll
    for (int mt = 0; mt < 2; mt++) {
#pragma unroll
        for (int nt = 0; nt < 8; nt++) {
#pragma unroll
            for (int half = 0; half < 2; half++) {
                int r = rbase + mt * 16 + half * 8;
                int c = cbase + nt * 8;
                size_t idx = (size_t)r * N + c;
                float v0 = acc[mt][nt][half * 2], v1 = acc[mt][nt][half * 2 + 1];
                if (op == 0) {
                    *(float2*)(Cf + idx) = make_float2(v0, v1);
                } else if (op == 1) {
                    float2 old = *(const float2*)(Cf + idx);
                    *(float2*)(Cf + idx) = make_float2(v0 + old.x, v1 + old.y);
                } else if (op == 4) {
                    float o0 = v0, o1 = v1;
                    if (c < 2048) {
                        int n = r & (Nn - 1);
                        int i = (c & 63) >> 1;
                        float co = Cos[n * 32 + i], si = Sin[n * 32 + i];
                        o0 = v0 * co - v1 * si;
                        o1 = v0 * si + v1 * co;
                    }
                    *(float2*)(Cf + idx) = make_float2(o0, o1);
                } else {
                    float p0, p1;
                    if (op == 2) { p0 = gelu_f(v0); p1 = gelu_f(v1); }
                    else {
                        float2 a2 = *(const float2*)(Aux + idx);
                        p0 = silu_f(a2.x) * v0; p1 = silu_f(a2.y) * v1;
                    }
                    uint32_t h_, l_;
                    split2(p0, p1, h_, l_);
                    *(uint32_t*)(Chi + idx) = h_;
                    *(uint32_t*)(Clo + idx) = l_;
                }
            }
        }
    }
}

__global__ void rmsnorm_kernel(const float* __restrict__ x, const float* __restrict__ w,
                               float* __restrict__ out, __nv_bfloat16* __restrict__ oh,
                               __nv_bfloat16* __restrict__ ol)
{
    __shared__ float red[256];
    int t = blockIdx.x;
    const float* xr = x + (size_t)t * Dn;
    float ss = 0.f;
    for (int i = threadIdx.x; i < Dn; i += 256) { float v = xr[i]; ss += v * v; }
    red[threadIdx.x] = ss; __syncthreads();
    for (int s = 128; s > 0; s >>= 1) {
        if (threadIdx.x < s) red[threadIdx.x] += red[threadIdx.x + s];
        __syncthreads();
    }
    float inv = rsqrtf(red[0] * (1.0f / Dn) + 1e-5f);
    float* orow = out + (size_t)t * Dn;
    __nv_bfloat16* ohr = oh + (size_t)t * Dn;
    __nv_bfloat16* olr = ol + (size_t)t * Dn;
    for (int i = threadIdx.x * 2; i < Dn; i += 512) {
        float a = xr[i] * inv * w[i], b = xr[i+1] * inv * w[i+1];
        orow[i] = a; orow[i+1] = b;
        uint32_t h_, l_;
        split2(a, b, h_, l_);
        *(uint32_t*)(ohr + i) = h_;
        *(uint32_t*)(olr + i) = l_;
    }
}

// ---------- HMMA flash attention: bf16x3 scores + bf16x3 PV ----------
// flash smem pitch: 64 features + 8 pad (FROWE) — 64x72x2 = 9216 B per tile
#define FROWE 72
#define FSM 61440
__global__ void __launch_bounds__(128, 3) flash_kernel(
    const float* __restrict__ qkv,
    __nv_bfloat16* __restrict__ outh, __nv_bfloat16* __restrict__ outl)
{
    extern __shared__ char smf[];
    const uint32_t sb = smem_u32(smf);
    const uint32_t Qh = sb, Ql = sb + 10240u, Kh = sb + 20480u, Kl = sb + 30720u,
                   Vh = sb + 40960u, Vl = sb + 51200u;
    const int qt = blockIdx.x, bh = blockIdx.y;
    const int b = bh >> 4, h = bh & 15;
    const int tid = threadIdx.x, lane = tid & 31, w = tid >> 5;
    const size_t base = (size_t)b * Nn * (3 * Dn) + h * HDn;
    const int q0 = qt * 64;
    const int r0 = lane >> 2, c2 = (lane & 3) << 1;

    for (int i = tid; i < 64 * 16; i += 128) {
        int rr = i >> 4, cc = (i & 15) << 2;
        float4 f = *(const float4*)(qkv + base + (size_t)(q0 + rr) * (3 * Dn) + cc);
        uint32_t h0, l0, h1, l1;
        split2(f.x, f.y, h0, l0);
        split2(f.z, f.w, h1, l1);
        uint32_t off = (uint32_t)(rr * FROWE + cc) * 2u;
        asm volatile("st.shared.v2.u32 [%0], {%1,%2};" :: "r"(Qh + off), "r"(h0), "r"(h1) : "memory");
        asm volatile("st.shared.v2.u32 [%0], {%1,%2};" :: "r"(Ql + off), "r"(l0), "r"(l1) : "memory");
    }

    float acc_o[8][4];
#pragma unroll
    for (int nt = 0; nt < 8; nt++)
#pragma unroll
        for (int j = 0; j < 4; j++) acc_o[nt][j] = 0.f;
    float m0 = -1e30f, m1 = -1e30f, l0s = 0.f, l1s = 0.f;

    const uint32_t a_off = (uint32_t)((lane & 15) * FROWE + ((lane >> 4) << 3)) * 2u
                           + (uint32_t)(w * 16 * FROWE) * 2u;
    const uint32_t b_off = (uint32_t)(((lane & 7) + ((lane >> 4) << 3)) * FROWE
                                      + (((lane >> 3) & 1) << 3)) * 2u;

    for (int kt = 0; kt <= qt; kt++) {
        __syncthreads();
        int k0 = kt * 64;
        for (int i = tid; i < 64 * 16; i += 128) {      // K
            int rr = i >> 4, cc = (i & 15) << 2;
            float4 f = *(const float4*)(qkv + base + Dn + (size_t)(k0 + rr) * (3 * Dn) + cc);
            uint32_t h0, l0, h1, l1;
            split2(f.x, f.y, h0, l0);
            split2(f.z, f.w, h1, l1);
            uint32_t off = (uint32_t)(rr * FROWE + cc) * 2u;
            asm volatile("st.shared.v2.u32 [%0], {%1,%2};" :: "r"(Kh + off), "r"(h0), "r"(h1) : "memory");
            asm volatile("st.shared.v2.u32 [%0], {%1,%2};" :: "r"(Kl + off), "r"(l0), "r"(l1) : "memory");
        }
#pragma unroll
        for (int it = 0; it < 4; it++) {                // V transposed
            int item = tid + it * 128;
            int rp = item & 31, cq = item >> 5;
            int rr = rp * 2, cc = cq * 4;
            const float* vs = qkv + base + 2 * Dn + (size_t)(k0 + rr) * (3 * Dn) + cc;
            float4 f0 = *(const float4*)(vs);
            float4 f1 = *(const float4*)(vs + 3 * Dn);
            float a0[4] = {f0.x, f0.y, f0.z, f0.w};
            float a1[4] = {f1.x, f1.y, f1.z, f1.w};
#pragma unroll
            for (int j = 0; j < 4; j++) {
                uint32_t hh, llv;
                split2(a0[j], a1[j], hh, llv);
                uint32_t off = (uint32_t)((cc + j) * FROWE + rr) * 2u;
                asm volatile("st.shared.u32 [%0], %1;" :: "r"(Vh + off), "r"(hh) : "memory");
                asm volatile("st.shared.u32 [%0], %1;" :: "r"(Vl + off), "r"(llv) : "memory");
            }
        }
        __syncthreads();

        float s[8][4];
#pragma unroll
        for (int nt = 0; nt < 8; nt++)
#pragma unroll
            for (int j = 0; j < 4; j++) s[nt][j] = 0.f;
#pragma unroll
        for (int kk = 0; kk < 4; kk++) {
            uint32_t kb = (uint32_t)(kk << 5);
            uint32_t qh[4], ql[4], kf[4][4];
            LDSM4(qh[0], qh[1], qh[2], qh[3], Qh + a_off + kb);
            LDSM4(ql[0], ql[1], ql[2], ql[3], Ql + a_off + kb);
#pragma unroll
            for (int ntp = 0; ntp < 4; ntp++)
                LDSM4(kf[ntp][0], kf[ntp][1], kf[ntp][2], kf[ntp][3],
                      Kh + b_off + (uint32_t)(ntp * 16) * (FROWE*2u) + kb);
#pragma unroll
            for (int nt = 0; nt < 8; nt++) {
                int ntp = nt >> 1, hi = (nt & 1) << 1;
                MMA16816(s[nt], qh[0], qh[1], qh[2], qh[3], kf[ntp][hi], kf[ntp][hi+1]);
            }
#pragma unroll
            for (int nt = 0; nt < 8; nt++) {
                int ntp = nt >> 1, hi = (nt & 1) << 1;
                MMA16816(s[nt], ql[0], ql[1], ql[2], ql[3], kf[ntp][hi], kf[ntp][hi+1]);
            }
#pragma unroll
            for (int ntp = 0; ntp < 4; ntp++)
                LDSM4(kf[ntp][0], kf[ntp][1], kf[ntp][2], kf[ntp][3],
                      Kl + b_off + (uint32_t)(ntp * 16) * (FROWE*2u) + kb);
#pragma unroll
            for (int nt = 0; nt < 8; nt++) {
                int ntp = nt >> 1, hi = (nt & 1) << 1;
                MMA16816(s[nt], qh[0], qh[1], qh[2], qh[3], kf[ntp][hi], kf[ntp][hi+1]);
            }
        }

        int row0g = q0 + w * 16 + r0, row1g = row0g + 8;
        float mx0 = -1e30f, mx1 = -1e30f;
#pragma unroll
        for (int nt = 0; nt < 8; nt++) {
            int cg = k0 + nt * 8 + c2;
#pragma unroll
            for (int j = 0; j < 4; j++) s[nt][j] *= 0.125f;
            if (kt == qt) {
                if (cg     > row0g) s[nt][0] = -1e30f;
                if (cg + 1 > row0g) s[nt][1] = -1e30f;
                if (cg     > row1g) s[nt][2] = -1e30f;
                if (cg + 1 > row1g) s[nt][3] = -1e30f;
            }
            mx0 = fmaxf(mx0, fmaxf(s[nt][0], s[nt][1]));
            mx1 = fmaxf(mx1, fmaxf(s[nt][2], s[nt][3]));
        }
        mx0 = fmaxf(mx0, __shfl_xor_sync(0xffffffffu, mx0, 1));
        mx0 = fmaxf(mx0, __shfl_xor_sync(0xffffffffu, mx0, 2));
        mx1 = fmaxf(mx1, __shfl_xor_sync(0xffffffffu, mx1, 1));
        mx1 = fmaxf(mx1, __shfl_xor_sync(0xffffffffu, mx1, 2));
        float mn0 = fmaxf(m0, mx0), mn1 = fmaxf(m1, mx1);
        float cr0 = expf(m0 - mn0), cr1 = expf(m1 - mn1);
        float ps0 = 0.f, ps1 = 0.f;
#pragma unroll
        for (int nt = 0; nt < 8; nt++) {
            s[nt][0] = expf(s[nt][0] - mn0); ps0 += s[nt][0];
            s[nt][1] = expf(s[nt][1] - mn0); ps0 += s[nt][1];
            s[nt][2] = expf(s[nt][2] - mn1); ps1 += s[nt][2];
            s[nt][3] = expf(s[nt][3] - mn1); ps1 += s[nt][3];
        }
        ps0 += __shfl_xor_sync(0xffffffffu, ps0, 1);
        ps0 += __shfl_xor_sync(0xffffffffu, ps0, 2);
        ps1 += __shfl_xor_sync(0xffffffffu, ps1, 1);
        ps1 += __shfl_xor_sync(0xffffffffu, ps1, 2);
        l0s = l0s * cr0 + ps0;
        l1s = l1s * cr1 + ps1;
        m0 = mn0; m1 = mn1;
#pragma unroll
        for (int nt = 0; nt < 8; nt++) {
            acc_o[nt][0] *= cr0; acc_o[nt][1] *= cr0;
            acc_o[nt][2] *= cr1; acc_o[nt][3] *= cr1;
        }

#pragma unroll
        for (int kk = 0; kk < 4; kk++) {
            uint32_t kb = (uint32_t)(kk << 5);
            uint32_t ph[4], pl[4], vf[4][4];
            split2(s[2*kk][0],   s[2*kk][1],   ph[0], pl[0]);
            split2(s[2*kk][2],   s[2*kk][3],   ph[1], pl[1]);
            split2(s[2*kk+1][0], s[2*kk+1][1], ph[2], pl[2]);
            split2(s[2*kk+1][2], s[2*kk+1][3], ph[3], pl[3]);
#pragma unroll
            for (int ntp = 0; ntp < 4; ntp++)
                LDSM4(vf[ntp][0], vf[ntp][1], vf[ntp][2], vf[ntp][3],
                      Vh + b_off + (uint32_t)(ntp * 16) * (FROWE*2u) + kb);
#pragma unroll
            for (int nt = 0; nt < 8; nt++) {
                int ntp = nt >> 1, hi = (nt & 1) << 1;
                MMA16816(acc_o[nt], ph[0], ph[1], ph[2], ph[3], vf[ntp][hi], vf[ntp][hi+1]);
            }
#pragma unroll
            for (int nt = 0; nt < 8; nt++) {
                int ntp = nt >> 1, hi = (nt & 1) << 1;
                MMA16816(acc_o[nt], pl[0], pl[1], pl[2], pl[3], vf[ntp][hi], vf[ntp][hi+1]);
            }
#pragma unroll
            for (int ntp = 0; ntp < 4; ntp++)
                LDSM4(vf[ntp][0], vf[ntp][1], vf[ntp][2], vf[ntp][3],
                      Vl + b_off + (uint32_t)(ntp * 16) * (FROWE*2u) + kb);
#pragma unroll
            for (int nt = 0; nt < 8; nt++) {
                int ntp = nt >> 1, hi = (nt & 1) << 1;
                MMA16816(acc_o[nt], ph[0], ph[1], ph[2], ph[3], vf[ntp][hi], vf[ntp][hi+1]);
            }
        }
    }

    float inv0 = 1.f / l0s, inv1 = 1.f / l1s;
    size_t ob0 = ((size_t)(b * Nn + q0 + w * 16 + r0)) * Dn + h * HDn;
    size_t ob1 = ob0 + (size_t)8 * Dn;
#pragma unroll
    for (int nt = 0; nt < 8; nt++) {
        int cc = nt * 8 + c2;
        uint32_t hh, llv;
        split2(acc_o[nt][0] * inv0, acc_o[nt][1] * inv0, hh, llv);
        *(uint32_t*)(outh + ob0 + cc) = hh;
        *(uint32_t*)(outl + ob0 + cc) = llv;
        split2(acc_o[nt][2] * inv1, acc_o[nt][3] * inv1, hh, llv);
        *(uint32_t*)(outh + ob1 + cc) = hh;
        *(uint32_t*)(outl + ob1 + cc) = llv;
    }
}

__global__ void gate_kernel(const float* __restrict__ xn, const float* __restrict__ wg,
                            float* __restrict__ raw, int* __restrict__ idx1,
                            int* __restrict__ idx2, int* __restrict__ keep,
                            float* __restrict__ g1o, float* __restrict__ g2o,
                            unsigned key0, unsigned key1)
{
    __shared__ float red[8 * 256];
    int t = blockIdx.x;
    const float* xr = xn + (size_t)t * Dn;
    float acc[8] = {0,0,0,0,0,0,0,0};
    for (int i = threadIdx.x; i < Dn; i += 256) {
        float v = xr[i];
        const float* wr = wg + (size_t)i * NEn;
#pragma unroll
        for (int e = 0; e < 8; e++) acc[e] += v * wr[e];
    }
#pragma unroll
    for (int e = 0; e < 8; e++) red[e * 256 + threadIdx.x] = acc[e];
    __syncthreads();
    for (int s = 128; s > 0; s >>= 1) {
        if (threadIdx.x < s) {
#pragma unroll
            for (int e = 0; e < 8; e++)
                red[e * 256 + threadIdx.x] += red[e * 256 + threadIdx.x + s];
        }
        __syncthreads();
    }
    if (threadIdx.x == 0) {
        float p[8];
        float mx = red[0];
#pragma unroll
        for (int e = 1; e < 8; e++) mx = fmaxf(mx, red[e * 256]);
        float sum = 0.f;
#pragma unroll
        for (int e = 0; e < 8; e++) { p[e] = expf(red[e * 256] - mx); sum += p[e]; }
#pragma unroll
        for (int e = 0; e < 8; e++) p[e] /= sum;
        int i1 = 0; float b1 = p[0];
#pragma unroll
        for (int e = 1; e < 8; e++) if (p[e] > b1) { b1 = p[e]; i1 = e; }
        int i2 = -1; float b2 = -1.f;
#pragma unroll
        for (int e = 0; e < 8; e++) if (e != i1 && p[e] > b2) { b2 = p[e]; i2 = e; }
        float denom = b1 + b2 + 1e-9f;
        float g1 = b1 / denom, g2 = b2 / denom;
        unsigned x0 = 0u, x1 = (unsigned)t;
        threefry2x32(key0, key1, x0, x1);
        unsigned bits = x0 ^ x1;
        float u = __uint_as_float((bits >> 9) | 0x3F800000u) - 1.0f;
        int kp = (u < (g2 / 0.2f)) ? 1 : 0;
#pragma unroll
        for (int e = 0; e < 8; e++) raw[t * NEn + e] = p[e];
        idx1[t] = i1; idx2[t] = i2; keep[t] = kp; g1o[t] = g1; g2o[t] = g2;
    }
}

__global__ void loss_sum_kernel(const float* __restrict__ raw, const int* __restrict__ idx1,
                                float* __restrict__ rawsum, float* __restrict__ cnt1)
{
    __shared__ float r1[256], r2[256];
    int be = blockIdx.x, b = be >> 3, e = be & 7;
    float s1 = 0.f, s2 = 0.f;
    for (int n = threadIdx.x; n < Nn; n += 256) {
        int t = b * Nn + n;
        s1 += raw[t * NEn + e];
        s2 += (idx1[t] == e) ? 1.f : 0.f;
    }
    r1[threadIdx.x] = s1; r2[threadIdx.x] = s2; __syncthreads();
    for (int s = 128; s > 0; s >>= 1) {
        if (threadIdx.x < s) {
            r1[threadIdx.x] += r1[threadIdx.x + s];
            r2[threadIdx.x] += r2[threadIdx.x + s];
        }
        __syncthreads();
    }
    if (threadIdx.x == 0) { rawsum[be] = r1[0]; cnt1[be] = r2[0]; }
}

__global__ void slots_kernel(const int* __restrict__ idx1, const int* __restrict__ idx2,
                             const int* __restrict__ keep, int* __restrict__ slot1,
                             int* __restrict__ slot2, const float* __restrict__ rawsum,
                             const float* __restrict__ cnt1, float* __restrict__ loss_out)
{
    __shared__ char si1[TOK], si2[TOK], skp[TOK];
    __shared__ float lred[32];
    int tid = threadIdx.x;
    for (int i = tid; i < TOK; i += 256) {
        si1[i] = (char)idx1[i]; si2[i] = (char)idx2[i]; skp[i] = (char)keep[i];
        slot1[i] = -1; slot2[i] = -1;
    }
    __syncthreads();
    if (tid < 32) {
        int b = tid >> 3, e = tid & 7;
        int base = (e * Bn + b) * CAPn;
        int c = 0;
        for (int n = 0; n < Nn; n++) {
            int t = b * Nn + n;
            if (si1[t] == e) { if (c < CAPn) slot1[t] = base + c; c++; }
        }
        int m1c = c < CAPn ? c : CAPn;
        int c2 = 0;
        for (int n = 0; n < Nn; n++) {
            int t = b * Nn + n;
            if (si2[t] == e && skp[t]) {
                int pos = m1c + c2; c2++;
                if (pos < CAPn) slot2[t] = base + pos;
            }
        }
        lred[tid] = rawsum[tid] * (1.f / Nn) * cnt1[tid] * (1.f / Nn);
    }
    __syncthreads();
    if (tid == 0) {
        float s = 0.f;
        for (int i = 0; i < 32; i++) s += lred[i];
        *loss_out += s * 0.02f;
    }
}

__global__ void scatter_kernel(const __nv_bfloat16* __restrict__ xnh,
                               const __nv_bfloat16* __restrict__ xnl,
                               const int* __restrict__ slot1, const int* __restrict__ slot2,
                               __nv_bfloat16* __restrict__ xeh, __nv_bfloat16* __restrict__ xel)
{
    int t = blockIdx.x;
    int s1 = slot1[t], s2 = slot2[t];
    if (s1 < 0 && s2 < 0) return;
    uint4 vh = ((const uint4*)(xnh + (size_t)t * Dn))[threadIdx.x];
    uint4 vl = ((const uint4*)(xnl + (size_t)t * Dn))[threadIdx.x];
    if (s1 >= 0) {
        ((uint4*)(xeh + (size_t)s1 * Dn))[threadIdx.x] = vh;
        ((uint4*)(xel + (size_t)s1 * Dn))[threadIdx.x] = vl;
    }
    if (s2 >= 0) {
        ((uint4*)(xeh + (size_t)s2 * Dn))[threadIdx.x] = vh;
        ((uint4*)(xel + (size_t)s2 * Dn))[threadIdx.x] = vl;
    }
}

__global__ void combine_kernel(const float* __restrict__ ye, const int* __restrict__ slot1,
                               const int* __restrict__ slot2, const float* __restrict__ g1,
                               const float* __restrict__ g2, float* __restrict__ x)
{
    int t = blockIdx.x;
    int s1 = slot1[t], s2 = slot2[t];
    if (s1 < 0 && s2 < 0) return;
    float a = (s1 >= 0) ? g1[t] : 0.f;
    float b = (s2 >= 0) ? g2[t] : 0.f;
    float4* xr = (float4*)(x + (size_t)t * Dn);
    float4 v = xr[threadIdx.x];
    if (s1 >= 0) {
        float4 w = ((const float4*)(ye + (size_t)s1 * Dn))[threadIdx.x];
        v.x += a * w.x; v.y += a * w.y; v.z += a * w.z; v.w += a * w.w;
    }
    if (s2 >= 0) {
        float4 w = ((const float4*)(ye + (size_t)s2 * Dn))[threadIdx.x];
        v.x += b * w.x; v.y += b * w.y; v.z += b * w.z; v.w += b * w.w;
    }
    xr[threadIdx.x] = v;
}

extern "C" void kernel_launch(void* const* d_in, const int* in_sizes, int n_in,
                              void* d_out, int out_size)
{
    const float* x    = (const float*)d_in[0];
    const float* cosb = (const float*)d_in[1];
    const float* sinb = (const float*)d_in[2];
    const float* ln   = (const float*)d_in[3];
    const float* wqkv = (const float*)d_in[4];
    const float* wo   = (const float*)d_in[5];
    const float* w1   = (const float*)d_in[6];
    const float* w2   = (const float*)d_in[7];
    const float* w3   = (const float*)d_in[8];
    const float* wg   = (const float*)d_in[9];
    const float* mw1  = (const float*)d_in[10];
    const float* mw2  = (const float*)d_in[11];
    float* xout = (float*)d_out;

    void* p;
    cudaGetSymbolAddress(&p, g_norm);  float* norm  = (float*)p;
    cudaGetSymbolAddress(&p, g_normh); __nv_bfloat16* normh = (__nv_bfloat16*)p;
    cudaGetSymbolAddress(&p, g_norml); __nv_bfloat16* norml = (__nv_bfloat16*)p;
    cudaGetSymbolAddress(&p, g_big);   float* big   = (float*)p;
    cudaGetSymbolAddress(&p, g_attnh); __nv_bfloat16* attnh = (__nv_bfloat16*)p;
    cudaGetSymbolAddress(&p, g_attnl); __nv_bfloat16* attnl = (__nv_bfloat16*)p;
    cudaGetSymbolAddress(&p, g_h1);    float* h1    = (float*)p;
    cudaGetSymbolAddress(&p, g_hidh);  __nv_bfloat16* hidh = (__nv_bfloat16*)p;
    cudaGetSymbolAddress(&p, g_hidl);  __nv_bfloat16* hidl = (__nv_bfloat16*)p;
    cudaGetSymbolAddress(&p, g_xeh);   __nv_bfloat16* xeh = (__nv_bfloat16*)p;
    cudaGetSymbolAddress(&p, g_xel);   __nv_bfloat16* xel = (__nv_bfloat16*)p;
    cudaGetSymbolAddress(&p, g_ye);    float* ye    = (float*)p;
    cudaGetSymbolAddress(&p, g_raw);   float* raw   = (float*)p;
    cudaGetSymbolAddress(&p, g_idx1);  int* idx1    = (int*)p;
    cudaGetSymbolAddress(&p, g_idx2);  int* idx2    = (int*)p;
    cudaGetSymbolAddress(&p, g_keep);  int* keep    = (int*)p;
    cudaGetSymbolAddress(&p, g_slot1); int* slot1   = (int*)p;
    cudaGetSymbolAddress(&p, g_slot2); int* slot2   = (int*)p;
    cudaGetSymbolAddress(&p, g_g1);    float* g1    = (float*)p;
    cudaGetSymbolAddress(&p, g_g2);    float* g2    = (float*)p;
    cudaGetSymbolAddress(&p, g_rawsum);float* rawsum= (float*)p;
    cudaGetSymbolAddress(&p, g_cnt1);  float* cnt1  = (float*)p;
    cudaGetSymbolAddress(&p, g_lossbuf); float* lossbuf = (float*)p;
    cudaGetSymbolAddress(&p, g_whi);   __nv_bfloat16* whi = (__nv_bfloat16*)p;
    cudaGetSymbolAddress(&p, g_wlo);   __nv_bfloat16* wlo = (__nv_bfloat16*)p;

    cudaFuncSetAttribute(flash_kernel, cudaFuncAttributeMaxDynamicSharedMemorySize, FSM);
    cudaFuncSetAttribute(mma_gemm, cudaFuncAttributeMaxDynamicSharedMemorySize, MGSMEM);

    float* lossp = (out_size > TOK * Dn) ? (xout + (size_t)TOK * Dn) : lossbuf;

    unsigned k1a, k1b, k2a, k2b;
    { unsigned a = 0u, b = 0u; threefry2x32(0u, 42u, a, b); k1a = a; k1b = b; }
    { unsigned a = 0u, b = 1u; threefry2x32(0u, 42u, a, b); k2a = a; k2b = b; }

    const long long sXE  = (long long)Bn * CAPn * Dn;
    const long long sHID = (long long)Bn * CAPn * MOEHn;
    dim3 wb(32, 8);
#define NILB (__nv_bfloat16*)0
#define NILF (const float*)0

    // items: 0 memcpy, 1 wprep(qkv), 2 rmsnorm, 3 qkv gemm, 4 memset, 5 flash <- profiled
    cudaMemcpyAsync(xout, x, (size_t)TOK * Dn * sizeof(float),
                    cudaMemcpyDeviceToDevice, 0);
    wprep_kernel<<<dim3(96, 32, 3),  wb>>>(wqkv, whi + QKV_OFF, wlo + QKV_OFF,
                                           1024, 3072, 1024LL*3072, 1024LL*3072);
    rmsnorm_kernel<<<TOK, 256>>>(xout, ln, norm, normh, norml);
    mma_gemm<<<dim3(24, 32, 1), 256, MGSMEM>>>(
        normh, norml, whi + QKV_OFF, wlo + QKV_OFF,
        big, NILB, NILB, NILF, cosb, sinb, TOK, 3072, 1024, 0, 0, 0, 4);
    cudaMemsetAsync(lossp, 0, sizeof(float), 0);
    flash_kernel<<<dim3(16, 64), 128, FSM>>>(big, attnh, attnl);

    wprep_kernel<<<dim3(32, 32, 3),  wb>>>(wo,  whi + WO_OFF,  wlo + WO_OFF,
                                           1024, 1024, 1024LL*1024, 1024LL*1024);
    wprep_kernel<<<dim3(88, 32, 3),  wb>>>(w1,  whi + W1_OFF,  wlo + W1_OFF,
                                           1024, 2816, 1024LL*2816, 1024LL*2816);
    wprep_kernel<<<dim3(88, 32, 3),  wb>>>(w3,  whi + W3_OFF,  wlo + W3_OFF,
                                           1024, 2816, 1024LL*2816, 1024LL*2816);
    wprep_kernel<<<dim3(32, 88, 3),  wb>>>(w2,  whi + W2_OFF,  wlo + W2_OFF,
                                           2816, 1024, 2816LL*1024, 2816LL*1024);
    wprep_kernel<<<dim3(64, 32, 16), wb>>>(mw1, whi + MW1_OFF, wlo + MW1_OFF,
                                           1024, 2048, 1024LL*2048, 1024LL*2048);
    wprep_kernel<<<dim3(32, 64, 16), wb>>>(mw2, whi + MW2_OFF, wlo + MW2_OFF,
                                           2048, 1024, 2048LL*1024, 2048LL*1024);

    auto attn_tail = [&](int la) {
        mma_gemm<<<dim3(8, 32, 1), 256, MGSMEM>>>(
            attnh, attnl,
            whi + WO_OFF + (long long)la * 1048576,
            wlo + WO_OFF + (long long)la * 1048576,
            xout, NILB, NILB, NILF, NILF, NILF, TOK, 1024, 1024, 0, 0, 0, 1);
    };
    auto attn_layer = [&](int la, int lnidx) {
        rmsnorm_kernel<<<TOK, 256>>>(xout, ln + (size_t)lnidx * Dn, norm, normh, norml);
        mma_gemm<<<dim3(24, 32, 1), 256, MGSMEM>>>(
            normh, norml,
            whi + QKV_OFF + (long long)la * 3145728,
            wlo + QKV_OFF + (long long)la * 3145728,
            big, NILB, NILB, NILF, cosb, sinb, TOK, 3072, 1024, 0, 0, 0, 4);
        flash_kernel<<<dim3(16, 64), 128, FSM>>>(big, attnh, attnl);
        attn_tail(la);
    };
    auto mlp_layer = [&](int lm, int lnidx) {
        rmsnorm_kernel<<<TOK, 256>>>(xout, ln + (size_t)lnidx * Dn, norm, normh, norml);
        mma_gemm<<<dim3(22, 32, 1), 256, MGSMEM>>>(
            normh, norml,
            whi + W1_OFF + (long long)lm * 2883584,
            wlo + W1_OFF + (long long)lm * 2883584,
            h1, NILB, NILB, NILF, NILF, NILF, TOK, 2816, 1024, 0, 0, 0, 0);
        mma_gemm<<<dim3(22, 32, 1), 256, MGSMEM>>>(
            normh, norml,
            whi + W3_OFF + (long long)lm * 2883584,
            wlo + W3_OFF + (long long)lm * 2883584,
            (float*)0, hidh, hidl, h1, NILF, NILF, TOK, 2816, 1024, 0, 0, 0, 3);
        mma_gemm<<<dim3(8, 32, 1), 256, MGSMEM>>>(
            hidh, hidl,
            whi + W2_OFF + (long long)lm * 2883584,
            wlo + W2_OFF + (long long)lm * 2883584,
            xout, NILB, NILB, NILF, NILF, NILF, TOK, 1024, 2816, 0, 0, 0, 1);
    };
    auto moe_layer = [&](int lo, int lnidx, unsigned ka, unsigned kbb) {
        rmsnorm_kernel<<<TOK, 256>>>(xout, ln + (size_t)lnidx * Dn, norm, normh, norml);
        gate_kernel<<<TOK, 256>>>(norm, wg + (size_t)lo * Dn * NEn,
                                  raw, idx1, idx2, keep, g1, g2, ka, kbb);
        loss_sum_kernel<<<Bn * NEn, 256>>>(raw, idx1, rawsum, cnt1);
        slots_kernel<<<1, 256>>>(idx1, idx2, keep, slot1, slot2, rawsum, cnt1, lossp);
        scatter_kernel<<<TOK, 128>>>(normh, norml, slot1, slot2, xeh, xel);
        mma_gemm<<<dim3(16, 5, 8), 256, MGSMEM>>>(
            xeh, xel,
            whi + MW1_OFF + (long long)lo * 16777216,
            wlo + MW1_OFF + (long long)lo * 16777216,
            (float*)0, hidh, hidl, NILF, NILF, NILF,
            Bn * CAPn, MOEHn, 1024, sXE, 2097152LL, sHID, 2);
        mma_gemm<<<dim3(8, 5, 8), 256, MGSMEM>>>(
            hidh, hidl,
            whi + MW2_OFF + (long long)lo * 16777216,
            wlo + MW2_OFF + (long long)lo * 16777216,
            ye, NILB, NILB, NILF, NILF, NILF,
            Bn * CAPn, 1024, 2048, sHID, 2097152LL, sXE, 0);
        combine_kernel<<<TOK, 256>>>(ye, slot1, slot2, g1, g2, xout);
    };

    attn_tail(0);               // layer-0 rmsnorm/qkv/flash issued above
    mlp_layer(0, 1);
    moe_layer(0, 2, k1a, k1b);
    mlp_layer(1, 3);
    attn_layer(1, 4);
    moe_layer(1, 5, k2a, k2b);
    attn_layer(2, 6);
    mlp_layer(2, 7);
}

// round 14
// speedup vs baseline: 2.0796x; 1.0434x over previous
#include <cuda_runtime.h>
#include <cuda_bf16.h>
#include <stdint.h>
#include <math.h>

#define Bn 4
#define Nn 1024
#define Dn 1024
#define NHn 16
#define HDn 64
#define FFHn 2816
#define MOEHn 2048
#define NEn 8
#define CAPn 160
#define TOK (Bn*Nn)
#define NSLOT (NEn*Bn*CAPn)

#define QKV_OFF 0LL
#define WO_OFF  9437184LL
#define W1_OFF  12582912LL
#define W3_OFF  21233664LL
#define W2_OFF  29884416LL
#define MW1_OFF 38535168LL
#define MW2_OFF 72089600LL
#define WTOTAL  105644032LL

typedef unsigned long long u64t;

static __device__ float g_norm[TOK*Dn];
static __device__ __nv_bfloat16 g_normh[TOK*Dn], g_norml[TOK*Dn];
static __device__ __nv_bfloat16 g_bigh[TOK*3*Dn], g_bigl[TOK*3*Dn];
static __device__ __nv_bfloat16 g_attnh[TOK*Dn], g_attnl[TOK*Dn];
static __device__ float g_h1[TOK*FFHn];
static __device__ __nv_bfloat16 g_hidh[TOK*FFHn], g_hidl[TOK*FFHn];
static __device__ __nv_bfloat16 g_xeh[NSLOT*Dn], g_xel[NSLOT*Dn];
static __device__ float g_ye[NSLOT*Dn];
static __device__ float g_raw [TOK*NEn];
static __device__ int   g_idx1[TOK], g_idx2[TOK], g_keep[TOK];
static __device__ int   g_slot1[TOK], g_slot2[TOK];
static __device__ float g_g1[TOK], g_g2[TOK];
static __device__ float g_rawsum[Bn*NEn], g_cnt1[Bn*NEn];
static __device__ float g_lossbuf[1];
static __device__ __nv_bfloat16 g_whi[WTOTAL];
static __device__ __nv_bfloat16 g_wlo[WTOTAL];

__host__ __device__ __forceinline__ void threefry2x32(unsigned k0, unsigned k1,
                                                      unsigned& x0, unsigned& x1)
{
    unsigned ks2 = k0 ^ k1 ^ 0x1BD11BDAu;
    x0 += k0; x1 += k1;
#define TFR(r) { x0 += x1; x1 = (x1<<(r))|(x1>>(32-(r))); x1 ^= x0; }
    TFR(13) TFR(15) TFR(26) TFR(6)
    x0 += k1;  x1 += ks2 + 1u;
    TFR(17) TFR(29) TFR(16) TFR(24)
    x0 += ks2; x1 += k0 + 2u;
    TFR(13) TFR(15) TFR(26) TFR(6)
    x0 += k0;  x1 += k1 + 3u;
    TFR(17) TFR(29) TFR(16) TFR(24)
    x0 += k1;  x1 += ks2 + 4u;
    TFR(13) TFR(15) TFR(26) TFR(6)
    x0 += ks2; x1 += k0 + 5u;
#undef TFR
}

__global__ void wprep_kernel(const float* __restrict__ W, __nv_bfloat16* __restrict__ hi,
                             __nv_bfloat16* __restrict__ lo, int K, int N,
                             long long sW, long long sO)
{
    __shared__ float t[32][33];
    W  += (long long)blockIdx.z * sW;
    hi += (long long)blockIdx.z * sO;
    lo += (long long)blockIdx.z * sO;
    int n0 = blockIdx.x * 32, k0 = blockIdx.y * 32;
#pragma unroll
    for (int j = 0; j < 4; j++)
        t[threadIdx.y + j*8][threadIdx.x] =
            W[(size_t)(k0 + threadIdx.y + j*8) * N + n0 + threadIdx.x];
    __syncthreads();
#pragma unroll
    for (int j = 0; j < 4; j++) {
        int n = n0 + threadIdx.y + j*8, k = k0 + threadIdx.x;
        float v = t[threadIdx.x][threadIdx.y + j*8];
        __nv_bfloat16 h = __float2bfloat16(v);
        hi[(size_t)n * K + k] = h;
        lo[(size_t)n * K + k] = __float2bfloat16(v - __bfloat162float(h));
    }
}

__device__ __forceinline__ uint32_t smem_u32(const void* p) {
    uint32_t a;
    asm("{ .reg .u64 t; cvta.to.shared.u64 t, %1; cvt.u32.u64 %0, t; }"
        : "=r"(a) : "l"(p));
    return a;
}
__device__ __forceinline__ void split2(float a, float b, uint32_t& hi, uint32_t& lo) {
    __nv_bfloat16 ha = __float2bfloat16(a), hb = __float2bfloat16(b);
    __nv_bfloat16 la = __float2bfloat16(a - __bfloat162float(ha));
    __nv_bfloat16 lb = __float2bfloat16(b - __bfloat162float(hb));
    hi = (uint32_t)__bfloat16_as_ushort(ha) | ((uint32_t)__bfloat16_as_ushort(hb) << 16);
    lo = (uint32_t)__bfloat16_as_ushort(la) | ((uint32_t)__bfloat16_as_ushort(lb) << 16);
}
__device__ __forceinline__ float gelu_f(float v) {
    return 0.5f * v * (1.0f + erff(v * 0.70710678118654752f));
}
__device__ __forceinline__ float silu_f(float v) {
    return v / (1.f + expf(-v));
}

#define LDSM4(r0,r1,r2,r3,addr) asm volatile( \
    "ldmatrix.sync.aligned.m8n8.x4.shared.b16 {%0,%1,%2,%3}, [%4];" \
    : "=r"(r0),"=r"(r1),"=r"(r2),"=r"(r3) : "r"(addr))

#define LDSM4T(r0,r1,r2,r3,addr) asm volatile( \
    "ldmatrix.sync.aligned.m8n8.x4.trans.shared.b16 {%0,%1,%2,%3}, [%4];" \
    : "=r"(r0),"=r"(r1),"=r"(r2),"=r"(r3) : "r"(addr))

#define MMA16816(c,a0,a1,a2,a3,b0,b1) asm volatile( \
    "mma.sync.aligned.m16n8k16.row.col.f32.bf16.bf16.f32 " \
    "{%0,%1,%2,%3}, {%4,%5,%6,%7}, {%8,%9}, {%0,%1,%2,%3};" \
    : "+f"((c)[0]),"+f"((c)[1]),"+f"((c)[2]),"+f"((c)[3]) \
    : "r"(a0),"r"(a1),"r"(a2),"r"(a3),"r"(b0),"r"(b1))

// ---------- HMMA GEMM: bf16x3 split, 2-stage cp.async, 2 CTAs/SM ----------
// op0: Cf=v  op1: Cf+=v  op2: split(gelu(v))  op3: split(silu(Aux)*v)
// op4: split(rope(v)) for cols<2048 else split(v) -> Chi/Clo
#define ROWE 40
#define TILEB 10240u
#define STGB  40960u
#define MGSMEM 81920
__global__ void __launch_bounds__(256, 2) mma_gemm(
    const __nv_bfloat16* __restrict__ Ah, const __nv_bfloat16* __restrict__ Al,
    const __nv_bfloat16* __restrict__ Bh, const __nv_bfloat16* __restrict__ Bl,
    float* __restrict__ Cf, __nv_bfloat16* __restrict__ Chi,
    __nv_bfloat16* __restrict__ Clo, const float* __restrict__ Aux,
    const float* __restrict__ Cos, const float* __restrict__ Sin,
    int M, int N, int K, long long sA, long long sB, long long sC, int op)
{
    extern __shared__ char smraw[];
    Ah += (long long)blockIdx.z * sA;  Al += (long long)blockIdx.z * sA;
    Bh += (long long)blockIdx.z * sB;  Bl += (long long)blockIdx.z * sB;
    if (Cf)  Cf  += (long long)blockIdx.z * sC;
    if (Chi) { Chi += (long long)blockIdx.z * sC; Clo += (long long)blockIdx.z * sC; }
    if (Aux) Aux += (long long)blockIdx.z * sC;
    const int tid = threadIdx.x, lane = tid & 31, w = tid >> 5;
    const int warp_m = w & 3, warp_n = w >> 2;
    const int row0 = blockIdx.y << 7, col0 = blockIdx.x << 7;
    const uint32_t sb = smem_u32(smraw);

    const __nv_bfloat16* Ahg = Ah + (size_t)row0 * K;
    const __nv_bfloat16* Alg = Al + (size_t)row0 * K;
    const __nv_bfloat16* Bhg = Bh + (size_t)col0 * K;
    const __nv_bfloat16* Blg = Bl + (size_t)col0 * K;
    const int S = K >> 5;

    float acc[2][8][4];
#pragma unroll
    for (int mt = 0; mt < 2; mt++)
#pragma unroll
        for (int nt = 0; nt < 8; nt++)
#pragma unroll
            for (int j = 0; j < 4; j++) acc[mt][nt][j] = 0.f;

    auto issue = [&](int s) {
        if (s < S) {
            uint32_t base = sb + (uint32_t)(s & 1) * STGB;
            int k0e = s << 5;
            const __nv_bfloat16* gsrc[4] = {Ahg, Alg, Bhg, Blg};
#pragma unroll
            for (int t4 = 0; t4 < 4; t4++) {
                const __nv_bfloat16* gp = gsrc[t4] + k0e;
                uint32_t tb = base + (uint32_t)t4 * TILEB;
#pragma unroll
                for (int i = 0; i < 2; i++) {
                    int c = (i << 8) + tid, row = c >> 2, q = c & 3;
                    uint32_t d = tb + (uint32_t)(row * (ROWE*2) + q * 16);
                    const void* sp = (const char*)(gp + (size_t)row * K) + (q << 4);
                    asm volatile("cp.async.cg.shared.global [%0], [%1], 16;"
                                 :: "r"(d), "l"(sp));
                }
            }
        }
        asm volatile("cp.async.commit_group;" ::: "memory");
    };

    const uint32_t a_off = (uint32_t)((lane & 15) * ROWE + ((lane >> 4) << 3)) * 2u;
    const uint32_t b_off = (uint32_t)(((lane & 7) + ((lane >> 4) << 3)) * ROWE
                                      + (((lane >> 3) & 1) << 3)) * 2u;
    const uint32_t a_mrow = (uint32_t)(warp_m * 32) * (ROWE * 2u);
    const uint32_t b_nrow = (uint32_t)(warp_n * 64) * (ROWE * 2u);

    auto compute = [&](uint32_t base) {
#pragma unroll
        for (int k16 = 0; k16 < 2; k16++) {
            uint32_t kb = (uint32_t)(k16 << 5);
            uint32_t b[4][4];
            uint32_t ah[2][4], al[2][4];
#pragma unroll
            for (int ntp = 0; ntp < 4; ntp++) {
                uint32_t bd = base + 2u * TILEB + b_nrow
                              + (uint32_t)(ntp * 16) * (ROWE*2u) + b_off + kb;
                LDSM4(b[ntp][0], b[ntp][1], b[ntp][2], b[ntp][3], bd);
            }
#pragma unroll
            for (int mt = 0; mt < 2; mt++) {
                uint32_t ad = base + a_mrow + (uint32_t)(mt * 16) * (ROWE*2u)
                              + a_off + kb;
                LDSM4(ah[mt][0], ah[mt][1], ah[mt][2], ah[mt][3], ad);
                LDSM4(al[mt][0], al[mt][1], al[mt][2], al[mt][3], ad + TILEB);
            }
#pragma unroll
            for (int mt = 0; mt < 2; mt++)
#pragma unroll
                for (int nt = 0; nt < 8; nt++) {
                    int ntp = nt >> 1, hi = (nt & 1) << 1;
                    MMA16816(acc[mt][nt], ah[mt][0], ah[mt][1], ah[mt][2], ah[mt][3],
                             b[ntp][hi], b[ntp][hi + 1]);
                }
#pragma unroll
            for (int mt = 0; mt < 2; mt++)
#pragma unroll
                for (int nt = 0; nt < 8; nt++) {
                    int ntp = nt >> 1, hi = (nt & 1) << 1;
                    MMA16816(acc[mt][nt], al[mt][0], al[mt][1], al[mt][2], al[mt][3],
                             b[ntp][hi], b[ntp][hi + 1]);
                }
#pragma unroll
            for (int ntp = 0; ntp < 4; ntp++) {
                uint32_t bd = base + 3u * TILEB + b_nrow
                              + (uint32_t)(ntp * 16) * (ROWE*2u) + b_off + kb;
                LDSM4(b[ntp][0], b[ntp][1], b[ntp][2], b[ntp][3], bd);
            }
#pragma unroll
            for (int mt = 0; mt < 2; mt++)
#pragma unroll
                for (int nt = 0; nt < 8; nt++) {
                    int ntp = nt >> 1, hi = (nt & 1) << 1;
                    MMA16816(acc[mt][nt], ah[mt][0], ah[mt][1], ah[mt][2], ah[mt][3],
                             b[ntp][hi], b[ntp][hi + 1]);
                }
        }
    };

    issue(0);
    for (int s = 0; s < S; s++) {
        issue(s + 1);
        asm volatile("cp.async.wait_group 1;" ::: "memory");
        __syncthreads();
        compute(sb + (uint32_t)(s & 1) * STGB);
        __syncthreads();
    }

    const int rbase = row0 + warp_m * 32 + (lane >> 2);
    const int cbase = col0 + warp_n * 64 + ((lane & 3) << 1);
#pragma unroll
    for (int mt = 0; mt < 2; mt++) {
#pragma unroll
        for (int nt = 0; nt < 8; nt++) {
#pragma unroll
            for (int half = 0; half < 2; half++) {
                int r = rbase + mt * 16 + half * 8;
                int c = cbase + nt * 8;
                size_t idx = (size_t)r * N + c;
                float v0 = acc[mt][nt][half * 2], v1 = acc[mt][nt][half * 2 + 1];
                if (op == 0) {
                    *(float2*)(Cf + idx) = make_float2(v0, v1);
                } else if (op == 1) {
                    float2 old = *(const float2*)(Cf + idx);
                    *(float2*)(Cf + idx) = make_float2(v0 + old.x, v1 + old.y);
                } else if (op == 4) {
                    float o0 = v0, o1 = v1;
                    if (c < 2048) {
                        int n = r & (Nn - 1);
                        int i = (c & 63) >> 1;
                        float co = Cos[n * 32 + i], si = Sin[n * 32 + i];
                        o0 = v0 * co - v1 * si;
                        o1 = v0 * si + v1 * co;
                    }
                    uint32_t h_, l_;
                    split2(o0, o1, h_, l_);
                    *(uint32_t*)(Chi + idx) = h_;
                    *(uint32_t*)(Clo + idx) = l_;
                } else {
                    float p0, p1;
                    if (op == 2) { p0 = gelu_f(v0); p1 = gelu_f(v1); }
                    else {
                        float2 a2 = *(const float2*)(Aux + idx);
                        p0 = silu_f(a2.x) * v0; p1 = silu_f(a2.y) * v1;
                    }
                    uint32_t h_, l_;
                    split2(p0, p1, h_, l_);
                    *(uint32_t*)(Chi + idx) = h_;
                    *(uint32_t*)(Clo + idx) = l_;
                }
            }
        }
    }
}

__global__ void rmsnorm_kernel(const float* __restrict__ x, const float* __restrict__ w,
                               float* __restrict__ out, __nv_bfloat16* __restrict__ oh,
                               __nv_bfloat16* __restrict__ ol)
{
    __shared__ float red[256];
    int t = blockIdx.x;
    const float* xr = x + (size_t)t * Dn;
    float ss = 0.f;
    for (int i = threadIdx.x; i < Dn; i += 256) { float v = xr[i]; ss += v * v; }
    red[threadIdx.x] = ss; __syncthreads();
    for (int s = 128; s > 0; s >>= 1) {
        if (threadIdx.x < s) red[threadIdx.x] += red[threadIdx.x + s];
        __syncthreads();
    }
    float inv = rsqrtf(red[0] * (1.0f / Dn) + 1e-5f);
    float* orow = out + (size_t)t * Dn;
    __nv_bfloat16* ohr = oh + (size_t)t * Dn;
    __nv_bfloat16* olr = ol + (size_t)t * Dn;
    for (int i = threadIdx.x * 2; i < Dn; i += 512) {
        float a = xr[i] * inv * w[i], b = xr[i+1] * inv * w[i+1];
        orow[i] = a; orow[i+1] = b;
        uint32_t h_, l_;
        split2(a, b, h_, l_);
        *(uint32_t*)(ohr + i) = h_;
        *(uint32_t*)(olr + i) = l_;
    }
}

// ---------- HMMA flash attention: bf16 hi/lo inputs, trans-ldmatrix V ----------
#define FROWE 72
#define FSM 61440
__global__ void __launch_bounds__(128, 3) flash_kernel(
    const __nv_bfloat16* __restrict__ qkvh, const __nv_bfloat16* __restrict__ qkvl,
    __nv_bfloat16* __restrict__ outh, __nv_bfloat16* __restrict__ outl)
{
    extern __shared__ char smf[];
    const uint32_t sb = smem_u32(smf);
    const uint32_t Qh = sb, Ql = sb + 10240u, Kh = sb + 20480u, Kl = sb + 30720u,
                   Vh = sb + 40960u, Vl = sb + 51200u;
    const int qt = (int)gridDim.x - 1 - (int)blockIdx.x;   // longest CTAs first
    const int bh = blockIdx.y;
    const int b = bh >> 4, h = bh & 15;
    const int tid = threadIdx.x, lane = tid & 31, w = tid >> 5;
    const size_t base = (size_t)(b * Nn) * 3072 + h * 64;
    const int q0 = qt * 64;
    const int r0 = lane >> 2, c2 = (lane & 3) << 1;

    // Q tiles via cp.async (group flushed together with first K/V)
    for (int i = tid; i < 512; i += 128) {
        int row = i >> 3, q = i & 7;
        uint32_t d = (uint32_t)(row * (FROWE*2) + q * 16);
        size_t go = base + (size_t)(q0 + row) * 3072 + q * 8;
        asm volatile("cp.async.cg.shared.global [%0], [%1], 16;"
                     :: "r"(Qh + d), "l"((const void*)(qkvh + go)));
        asm volatile("cp.async.cg.shared.global [%0], [%1], 16;"
                     :: "r"(Ql + d), "l"((const void*)(qkvl + go)));
    }
    asm volatile("cp.async.commit_group;" ::: "memory");

    float acc_o[8][4];
#pragma unroll
    for (int nt = 0; nt < 8; nt++)
#pragma unroll
        for (int j = 0; j < 4; j++) acc_o[nt][j] = 0.f;
    float m0 = -1e30f, m1 = -1e30f, l0s = 0.f, l1s = 0.f;

    const uint32_t a_off = (uint32_t)((lane & 15) * FROWE + ((lane >> 4) << 3)) * 2u
                           + (uint32_t)(w * 16 * FROWE) * 2u;
    const uint32_t b_off = (uint32_t)(((lane & 7) + ((lane >> 4) << 3)) * FROWE
                                      + (((lane >> 3) & 1) << 3)) * 2u;
    const uint32_t v_off = (uint32_t)((((lane & 7) + (((lane >> 3) & 1) << 3)) * FROWE
                                      + ((lane >> 4) << 3)) * 2);

    for (int kt = 0; kt <= qt; kt++) {
        int k0 = kt * 64;
        for (int i = tid; i < 512; i += 128) {          // K + V tiles
            int row = i >> 3, q = i & 7;
            uint32_t d = (uint32_t)(row * (FROWE*2) + q * 16);
            size_t go = base + (size_t)(k0 + row) * 3072 + q * 8;
            asm volatile("cp.async.cg.shared.global [%0], [%1], 16;"
                         :: "r"(Kh + d), "l"((const void*)(qkvh + go + 1024)));
            asm volatile("cp.async.cg.shared.global [%0], [%1], 16;"
                         :: "r"(Kl + d), "l"((const void*)(qkvl + go + 1024)));
            asm volatile("cp.async.cg.shared.global [%0], [%1], 16;"
                         :: "r"(Vh + d), "l"((const void*)(qkvh + go + 2048)));
            asm volatile("cp.async.cg.shared.global [%0], [%1], 16;"
                         :: "r"(Vl + d), "l"((const void*)(qkvl + go + 2048)));
        }
        asm volatile("cp.async.commit_group;" ::: "memory");
        asm volatile("cp.async.wait_group 0;" ::: "memory");
        __syncthreads();

        // S = Q K^T (bf16x3)
        float s[8][4];
#pragma unroll
        for (int nt = 0; nt < 8; nt++)
#pragma unroll
            for (int j = 0; j < 4; j++) s[nt][j] = 0.f;
#pragma unroll
        for (int kk = 0; kk < 4; kk++) {
            uint32_t kb = (uint32_t)(kk << 5);
            uint32_t qh[4], ql[4], kf[4][4];
            LDSM4(qh[0], qh[1], qh[2], qh[3], Qh + a_off + kb);
            LDSM4(ql[0], ql[1], ql[2], ql[3], Ql + a_off + kb);
#pragma unroll
            for (int ntp = 0; ntp < 4; ntp++)
                LDSM4(kf[ntp][0], kf[ntp][1], kf[ntp][2], kf[ntp][3],
                      Kh + b_off + (uint32_t)(ntp * 16) * (FROWE*2u) + kb);
#pragma unroll
            for (int nt = 0; nt < 8; nt++) {
                int ntp = nt >> 1, hi = (nt & 1) << 1;
                MMA16816(s[nt], qh[0], qh[1], qh[2], qh[3], kf[ntp][hi], kf[ntp][hi+1]);
            }
#pragma unroll
            for (int nt = 0; nt < 8; nt++) {
                int ntp = nt >> 1, hi = (nt & 1) << 1;
                MMA16816(s[nt], ql[0], ql[1], ql[2], ql[3], kf[ntp][hi], kf[ntp][hi+1]);
            }
#pragma unroll
            for (int ntp = 0; ntp < 4; ntp++)
                LDSM4(kf[ntp][0], kf[ntp][1], kf[ntp][2], kf[ntp][3],
                      Kl + b_off + (uint32_t)(ntp * 16) * (FROWE*2u) + kb);
#pragma unroll
            for (int nt = 0; nt < 8; nt++) {
                int ntp = nt >> 1, hi = (nt & 1) << 1;
                MMA16816(s[nt], qh[0], qh[1], qh[2], qh[3], kf[ntp][hi], kf[ntp][hi+1]);
            }
        }

        // online softmax
        int row0g = q0 + w * 16 + r0, row1g = row0g + 8;
        float mx0 = -1e30f, mx1 = -1e30f;
#pragma unroll
        for (int nt = 0; nt < 8; nt++) {
            int cg = k0 + nt * 8 + c2;
#pragma unroll
            for (int j = 0; j < 4; j++) s[nt][j] *= 0.125f;
            if (kt == qt) {
                if (cg     > row0g) s[nt][0] = -1e30f;
                if (cg + 1 > row0g) s[nt][1] = -1e30f;
                if (cg     > row1g) s[nt][2] = -1e30f;
                if (cg + 1 > row1g) s[nt][3] = -1e30f;
            }
            mx0 = fmaxf(mx0, fmaxf(s[nt][0], s[nt][1]));
            mx1 = fmaxf(mx1, fmaxf(s[nt][2], s[nt][3]));
        }
        mx0 = fmaxf(mx0, __shfl_xor_sync(0xffffffffu, mx0, 1));
        mx0 = fmaxf(mx0, __shfl_xor_sync(0xffffffffu, mx0, 2));
        mx1 = fmaxf(mx1, __shfl_xor_sync(0xffffffffu, mx1, 1));
        mx1 = fmaxf(mx1, __shfl_xor_sync(0xffffffffu, mx1, 2));
        float mn0 = fmaxf(m0, mx0), mn1 = fmaxf(m1, mx1);
        float cr0 = expf(m0 - mn0), cr1 = expf(m1 - mn1);
        float ps0 = 0.f, ps1 = 0.f;
#pragma unroll
        for (int nt = 0; nt < 8; nt++) {
            s[nt][0] = expf(s[nt][0] - mn0); ps0 += s[nt][0];
            s[nt][1] = expf(s[nt][1] - mn0); ps0 += s[nt][1];
            s[nt][2] = expf(s[nt][2] - mn1); ps1 += s[nt][2];
            s[nt][3] = expf(s[nt][3] - mn1); ps1 += s[nt][3];
        }
        ps0 += __shfl_xor_sync(0xffffffffu, ps0, 1);
        ps0 += __shfl_xor_sync(0xffffffffu, ps0, 2);
        ps1 += __shfl_xor_sync(0xffffffffu, ps1, 1);
        ps1 += __shfl_xor_sync(0xffffffffu, ps1, 2);
        l0s = l0s * cr0 + ps0;
        l1s = l1s * cr1 + ps1;
        m0 = mn0; m1 = mn1;
#pragma unroll
        for (int nt = 0; nt < 8; nt++) {
            acc_o[nt][0] *= cr0; acc_o[nt][1] *= cr0;
            acc_o[nt][2] *= cr1; acc_o[nt][3] *= cr1;
        }

        // O += P V (bf16x3), V via trans ldmatrix on [k][d] tiles
#pragma unroll
        for (int kk = 0; kk < 4; kk++) {
            uint32_t krow = (uint32_t)(kk * 16) * (FROWE*2u);
            uint32_t ph[4], pl[4], vf[4][4];
            split2(s[2*kk][0],   s[2*kk][1],   ph[0], pl[0]);
            split2(s[2*kk][2],   s[2*kk][3],   ph[1], pl[1]);
            split2(s[2*kk+1][0], s[2*kk+1][1], ph[2], pl[2]);
            split2(s[2*kk+1][2], s[2*kk+1][3], ph[3], pl[3]);
#pragma unroll
            for (int ntp = 0; ntp < 4; ntp++)
                LDSM4T(vf[ntp][0], vf[ntp][1], vf[ntp][2], vf[ntp][3],
                       Vh + v_off + krow + (uint32_t)(ntp * 16) * 2u);
#pragma unroll
            for (int nt = 0; nt < 8; nt++) {
                int ntp = nt >> 1, hi = (nt & 1) << 1;
                MMA16816(acc_o[nt], ph[0], ph[1], ph[2], ph[3], vf[ntp][hi], vf[ntp][hi+1]);
            }
#pragma unroll
            for (int nt = 0; nt < 8; nt++) {
                int ntp = nt >> 1, hi = (nt & 1) << 1;
                MMA16816(acc_o[nt], pl[0], pl[1], pl[2], pl[3], vf[ntp][hi], vf[ntp][hi+1]);
            }
#pragma unroll
            for (int ntp = 0; ntp < 4; ntp++)
                LDSM4T(vf[ntp][0], vf[ntp][1], vf[ntp][2], vf[ntp][3],
                       Vl + v_off + krow + (uint32_t)(ntp * 16) * 2u);
#pragma unroll
            for (int nt = 0; nt < 8; nt++) {
                int ntp = nt >> 1, hi = (nt & 1) << 1;
                MMA16816(acc_o[nt], ph[0], ph[1], ph[2], ph[3], vf[ntp][hi], vf[ntp][hi+1]);
            }
        }
        __syncthreads();
    }

    float inv0 = 1.f / l0s, inv1 = 1.f / l1s;
    size_t ob0 = ((size_t)(b * Nn + q0 + w * 16 + r0)) * Dn + h * HDn;
    size_t ob1 = ob0 + (size_t)8 * Dn;
#pragma unroll
    for (int nt = 0; nt < 8; nt++) {
        int cc = nt * 8 + c2;
        uint32_t hh, llv;
        split2(acc_o[nt][0] * inv0, acc_o[nt][1] * inv0, hh, llv);
        *(uint32_t*)(outh + ob0 + cc) = hh;
        *(uint32_t*)(outl + ob0 + cc) = llv;
        split2(acc_o[nt][2] * inv1, acc_o[nt][3] * inv1, hh, llv);
        *(uint32_t*)(outh + ob1 + cc) = hh;
        *(uint32_t*)(outl + ob1 + cc) = llv;
    }
}

__global__ void gate_kernel(const float* __restrict__ xn, const float* __restrict__ wg,
                            float* __restrict__ raw, int* __restrict__ idx1,
                            int* __restrict__ idx2, int* __restrict__ keep,
                            float* __restrict__ g1o, float* __restrict__ g2o,
                            unsigned key0, unsigned key1)
{
    __shared__ float red[8 * 256];
    int t = blockIdx.x;
    const float* xr = xn + (size_t)t * Dn;
    float acc[8] = {0,0,0,0,0,0,0,0};
    for (int i = threadIdx.x; i < Dn; i += 256) {
        float v = xr[i];
        const float* wr = wg + (size_t)i * NEn;
#pragma unroll
        for (int e = 0; e < 8; e++) acc[e] += v * wr[e];
    }
#pragma unroll
    for (int e = 0; e < 8; e++) red[e * 256 + threadIdx.x] = acc[e];
    __syncthreads();
    for (int s = 128; s > 0; s >>= 1) {
        if (threadIdx.x < s) {
#pragma unroll
            for (int e = 0; e < 8; e++)
                red[e * 256 + threadIdx.x] += red[e * 256 + threadIdx.x + s];
        }
        __syncthreads();
    }
    if (threadIdx.x == 0) {
        float p[8];
        float mx = red[0];
#pragma unroll
        for (int e = 1; e < 8; e++) mx = fmaxf(mx, red[e * 256]);
        float sum = 0.f;
#pragma unroll
        for (int e = 0; e < 8; e++) { p[e] = expf(red[e * 256] - mx); sum += p[e]; }
#pragma unroll
        for (int e = 0; e < 8; e++) p[e] /= sum;
        int i1 = 0; float b1 = p[0];
#pragma unroll
        for (int e = 1; e < 8; e++) if (p[e] > b1) { b1 = p[e]; i1 = e; }
        int i2 = -1; float b2 = -1.f;
#pragma unroll
        for (int e = 0; e < 8; e++) if (e != i1 && p[e] > b2) { b2 = p[e]; i2 = e; }
        float denom = b1 + b2 + 1e-9f;
        float g1 = b1 / denom, g2 = b2 / denom;
        unsigned x0 = 0u, x1 = (unsigned)t;
        threefry2x32(key0, key1, x0, x1);
        unsigned bits = x0 ^ x1;
        float u = __uint_as_float((bits >> 9) | 0x3F800000u) - 1.0f;
        int kp = (u < (g2 / 0.2f)) ? 1 : 0;
#pragma unroll
        for (int e = 0; e < 8; e++) raw[t * NEn + e] = p[e];
        idx1[t] = i1; idx2[t] = i2; keep[t] = kp; g1o[t] = g1; g2o[t] = g2;
    }
}

__global__ void loss_sum_kernel(const float* __restrict__ raw, const int* __restrict__ idx1,
                                float* __restrict__ rawsum, float* __restrict__ cnt1)
{
    __shared__ float r1[256], r2[256];
    int be = blockIdx.x, b = be >> 3, e = be & 7;
    float s1 = 0.f, s2 = 0.f;
    for (int n = threadIdx.x; n < Nn; n += 256) {
        int t = b * Nn + n;
        s1 += raw[t * NEn + e];
        s2 += (idx1[t] == e) ? 1.f : 0.f;
    }
    r1[threadIdx.x] = s1; r2[threadIdx.x] = s2; __syncthreads();
    for (int s = 128; s > 0; s >>= 1) {
        if (threadIdx.x < s) {
            r1[threadIdx.x] += r1[threadIdx.x + s];
            r2[threadIdx.x] += r2[threadIdx.x + s];
        }
        __syncthreads();
    }
    if (threadIdx.x == 0) { rawsum[be] = r1[0]; cnt1[be] = r2[0]; }
}

__global__ void slots_kernel(const int* __restrict__ idx1, const int* __restrict__ idx2,
                             const int* __restrict__ keep, int* __restrict__ slot1,
                             int* __restrict__ slot2, const float* __restrict__ rawsum,
                             const float* __restrict__ cnt1, float* __restrict__ loss_out)
{
    __shared__ char si1[TOK], si2[TOK], skp[TOK];
    __shared__ float lred[32];
    int tid = threadIdx.x;
    for (int i = tid; i < TOK; i += 256) {
        si1[i] = (char)idx1[i]; si2[i] = (char)idx2[i]; skp[i] = (char)keep[i];
        slot1[i] = -1; slot2[i] = -1;
    }
    __syncthreads();
    if (tid < 32) {
        int b = tid >> 3, e = tid & 7;
        int base = (e * Bn + b) * CAPn;
        int c = 0;
        for (int n = 0; n < Nn; n++) {
            int t = b * Nn + n;
            if (si1[t] == e) { if (c < CAPn) slot1[t] = base + c; c++; }
        }
        int m1c = c < CAPn ? c : CAPn;
        int c2 = 0;
        for (int n = 0; n < Nn; n++) {
            int t = b * Nn + n;
            if (si2[t] == e && skp[t]) {
                int pos = m1c + c2; c2++;
                if (pos < CAPn) slot2[t] = base + pos;
            }
        }
        lred[tid] = rawsum[tid] * (1.f / Nn) * cnt1[tid] * (1.f / Nn);
    }
    __syncthreads();
    if (tid == 0) {
        float s = 0.f;
        for (int i = 0; i < 32; i++) s += lred[i];
        *loss_out += s * 0.02f;
    }
}

__global__ void scatter_kernel(const __nv_bfloat16* __restrict__ xnh,
                               const __nv_bfloat16* __restrict__ xnl,
                               const int* __restrict__ slot1, const int* __restrict__ slot2,
                               __nv_bfloat16* __restrict__ xeh, __nv_bfloat16* __restrict__ xel)
{
    int t = blockIdx.x;
    int s1 = slot1[t], s2 = slot2[t];
    if (s1 < 0 && s2 < 0) return;
    uint4 vh = ((const uint4*)(xnh + (size_t)t * Dn))[threadIdx.x];
    uint4 vl = ((const uint4*)(xnl + (size_t)t * Dn))[threadIdx.x];
    if (s1 >= 0) {
        ((uint4*)(xeh + (size_t)s1 * Dn))[threadIdx.x] = vh;
        ((uint4*)(xel + (size_t)s1 * Dn))[threadIdx.x] = vl;
    }
    if (s2 >= 0) {
        ((uint4*)(xeh + (size_t)s2 * Dn))[threadIdx.x] = vh;
        ((uint4*)(xel + (size_t)s2 * Dn))[threadIdx.x] = vl;
    }
}

__global__ void combine_kernel(const float* __restrict__ ye, const int* __restrict__ slot1,
                               const int* __restrict__ slot2, const float* __restrict__ g1,
                               const float* __restrict__ g2, float* __restrict__ x)
{
    int t = blockIdx.x;
    int s1 = slot1[t], s2 = slot2[t];
    if (s1 < 0 && s2 < 0) return;
    float a = (s1 >= 0) ? g1[t] : 0.f;
    float b = (s2 >= 0) ? g2[t] : 0.f;
    float4* xr = (float4*)(x + (size_t)t * Dn);
    float4 v = xr[threadIdx.x];
    if (s1 >= 0) {
        float4 w = ((const float4*)(ye + (size_t)s1 * Dn))[threadIdx.x];
        v.x += a * w.x; v.y += a * w.y; v.z += a * w.z; v.w += a * w.w;
    }
    if (s2 >= 0) {
        float4 w = ((const float4*)(ye + (size_t)s2 * Dn))[threadIdx.x];
        v.x += b * w.x; v.y += b * w.y; v.z += b * w.z; v.w += b * w.w;
    }
    xr[threadIdx.x] = v;
}

extern "C" void kernel_launch(void* const* d_in, const int* in_sizes, int n_in,
                              void* d_out, int out_size)
{
    const float* x    = (const float*)d_in[0];
    const float* cosb = (const float*)d_in[1];
    const float* sinb = (const float*)d_in[2];
    const float* ln   = (const float*)d_in[3];
    const float* wqkv = (const float*)d_in[4];
    const float* wo   = (const float*)d_in[5];
    const float* w1   = (const float*)d_in[6];
    const float* w2   = (const float*)d_in[7];
    const float* w3   = (const float*)d_in[8];
    const float* wg   = (const float*)d_in[9];
    const float* mw1  = (const float*)d_in[10];
    const float* mw2  = (const float*)d_in[11];
    float* xout = (float*)d_out;

    void* p;
    cudaGetSymbolAddress(&p, g_norm);  float* norm  = (float*)p;
    cudaGetSymbolAddress(&p, g_normh); __nv_bfloat16* normh = (__nv_bfloat16*)p;
    cudaGetSymbolAddress(&p, g_norml); __nv_bfloat16* norml = (__nv_bfloat16*)p;
    cudaGetSymbolAddress(&p, g_bigh);  __nv_bfloat16* bigh = (__nv_bfloat16*)p;
    cudaGetSymbolAddress(&p, g_bigl);  __nv_bfloat16* bigl = (__nv_bfloat16*)p;
    cudaGetSymbolAddress(&p, g_attnh); __nv_bfloat16* attnh = (__nv_bfloat16*)p;
    cudaGetSymbolAddress(&p, g_attnl); __nv_bfloat16* attnl = (__nv_bfloat16*)p;
    cudaGetSymbolAddress(&p, g_h1);    float* h1    = (float*)p;
    cudaGetSymbolAddress(&p, g_hidh);  __nv_bfloat16* hidh = (__nv_bfloat16*)p;
    cudaGetSymbolAddress(&p, g_hidl);  __nv_bfloat16* hidl = (__nv_bfloat16*)p;
    cudaGetSymbolAddress(&p, g_xeh);   __nv_bfloat16* xeh = (__nv_bfloat16*)p;
    cudaGetSymbolAddress(&p, g_xel);   __nv_bfloat16* xel = (__nv_bfloat16*)p;
    cudaGetSymbolAddress(&p, g_ye);    float* ye    = (float*)p;
    cudaGetSymbolAddress(&p, g_raw);   float* raw   = (float*)p;
    cudaGetSymbolAddress(&p, g_idx1);  int* idx1    = (int*)p;
    cudaGetSymbolAddress(&p, g_idx2);  int* idx2    = (int*)p;
    cudaGetSymbolAddress(&p, g_keep);  int* keep    = (int*)p;
    cudaGetSymbolAddress(&p, g_slot1); int* slot1   = (int*)p;
    cudaGetSymbolAddress(&p, g_slot2); int* slot2   = (int*)p;
    cudaGetSymbolAddress(&p, g_g1);    float* g1    = (float*)p;
    cudaGetSymbolAddress(&p, g_g2);    float* g2    = (float*)p;
    cudaGetSymbolAddress(&p, g_rawsum);float* rawsum= (float*)p;
    cudaGetSymbolAddress(&p, g_cnt1);  float* cnt1  = (float*)p;
    cudaGetSymbolAddress(&p, g_lossbuf); float* lossbuf = (float*)p;
    cudaGetSymbolAddress(&p, g_whi);   __nv_bfloat16* whi = (__nv_bfloat16*)p;
    cudaGetSymbolAddress(&p, g_wlo);   __nv_bfloat16* wlo = (__nv_bfloat16*)p;

    cudaFuncSetAttribute(flash_kernel, cudaFuncAttributeMaxDynamicSharedMemorySize, FSM);
    cudaFuncSetAttribute(mma_gemm, cudaFuncAttributeMaxDynamicSharedMemorySize, MGSMEM);

    float* lossp = (out_size > TOK * Dn) ? (xout + (size_t)TOK * Dn) : lossbuf;

    unsigned k1a, k1b, k2a, k2b;
    { unsigned a = 0u, b = 0u; threefry2x32(0u, 42u, a, b); k1a = a; k1b = b; }
    { unsigned a = 0u, b = 1u; threefry2x32(0u, 42u, a, b); k2a = a; k2b = b; }

    const long long sXE  = (long long)Bn * CAPn * Dn;
    const long long sHID = (long long)Bn * CAPn * MOEHn;
    dim3 wb(32, 8);
#define NILB (__nv_bfloat16*)0
#define NILF (const float*)0

    // items: 0 memcpy, 1 wprep(qkv), 2 rmsnorm, 3 qkv gemm, 4 memset, 5 flash <- profiled
    cudaMemcpyAsync(xout, x, (size_t)TOK * Dn * sizeof(float),
                    cudaMemcpyDeviceToDevice, 0);
    wprep_kernel<<<dim3(96, 32, 3),  wb>>>(wqkv, whi + QKV_OFF, wlo + QKV_OFF,
                                           1024, 3072, 1024LL*3072, 1024LL*3072);
    rmsnorm_kernel<<<TOK, 256>>>(xout, ln, norm, normh, norml);
    mma_gemm<<<dim3(24, 32, 1), 256, MGSMEM>>>(
        normh, norml, whi + QKV_OFF, wlo + QKV_OFF,
        (float*)0, bigh, bigl, NILF, cosb, sinb, TOK, 3072, 1024, 0, 0, 0, 4);
    cudaMemsetAsync(lossp, 0, sizeof(float), 0);
    flash_kernel<<<dim3(16, 64), 128, FSM>>>(bigh, bigl, attnh, attnl);

    wprep_kernel<<<dim3(32, 32, 3),  wb>>>(wo,  whi + WO_OFF,  wlo + WO_OFF,
                                           1024, 1024, 1024LL*1024, 1024LL*1024);
    wprep_kernel<<<dim3(88, 32, 3),  wb>>>(w1,  whi + W1_OFF,  wlo + W1_OFF,
                                           1024, 2816, 1024LL*2816, 1024LL*2816);
    wprep_kernel<<<dim3(88, 32, 3),  wb>>>(w3,  whi + W3_OFF,  wlo + W3_OFF,
                                           1024, 2816, 1024LL*2816, 1024LL*2816);
    wprep_kernel<<<dim3(32, 88, 3),  wb>>>(w2,  whi + W2_OFF,  wlo + W2_OFF,
                                           2816, 1024, 2816LL*1024, 2816LL*1024);
    wprep_kernel<<<dim3(64, 32, 16), wb>>>(mw1, whi + MW1_OFF, wlo + MW1_OFF,
                                           1024, 2048, 1024LL*2048, 1024LL*2048);
    wprep_kernel<<<dim3(32, 64, 16), wb>>>(mw2, whi + MW2_OFF, wlo + MW2_OFF,
                                           2048, 1024, 2048LL*1024, 2048LL*1024);

    auto attn_tail = [&](int la) {
        mma_gemm<<<dim3(8, 32, 1), 256, MGSMEM>>>(
            attnh, attnl,
            whi + WO_OFF + (long long)la * 1048576,
            wlo + WO_OFF + (long long)la * 1048576,
            xout, NILB, NILB, NILF, NILF, NILF, TOK, 1024, 1024, 0, 0, 0, 1);
    };
    auto attn_layer = [&](int la, int lnidx) {
        rmsnorm_kernel<<<TOK, 256>>>(xout, ln + (size_t)lnidx * Dn, norm, normh, norml);
        mma_gemm<<<dim3(24, 32, 1), 256, MGSMEM>>>(
            normh, norml,
            whi + QKV_OFF + (long long)la * 3145728,
            wlo + QKV_OFF + (long long)la * 3145728,
            (float*)0, bigh, bigl, NILF, cosb, sinb, TOK, 3072, 1024, 0, 0, 0, 4);
        flash_kernel<<<dim3(16, 64), 128, FSM>>>(bigh, bigl, attnh, attnl);
        attn_tail(la);
    };
    auto mlp_layer = [&](int lm, int lnidx) {
        rmsnorm_kernel<<<TOK, 256>>>(xout, ln + (size_t)lnidx * Dn, norm, normh, norml);
        mma_gemm<<<dim3(22, 32, 1), 256, MGSMEM>>>(
            normh, norml,
            whi + W1_OFF + (long long)lm * 2883584,
            wlo + W1_OFF + (long long)lm * 2883584,
            h1, NILB, NILB, NILF, NILF, NILF, TOK, 2816, 1024, 0, 0, 0, 0);
        mma_gemm<<<dim3(22, 32, 1), 256, MGSMEM>>>(
            normh, norml,
            whi + W3_OFF + (long long)lm * 2883584,
            wlo + W3_OFF + (long long)lm * 2883584,
            (float*)0, hidh, hidl, h1, NILF, NILF, TOK, 2816, 1024, 0, 0, 0, 3);
        mma_gemm<<<dim3(8, 32, 1), 256, MGSMEM>>>(
            hidh, hidl,
            whi + W2_OFF + (long long)lm * 2883584,
            wlo + W2_OFF + (long long)lm * 2883584,
            xout, NILB, NILB, NILF, NILF, NILF, TOK, 1024, 2816, 0, 0, 0, 1);
    };
    auto moe_layer = [&](int lo, int lnidx, unsigned ka, unsigned kbb) {
        rmsnorm_kernel<<<TOK, 256>>>(xout, ln + (size_t)lnidx * Dn, norm, normh, norml);
        gate_kernel<<<TOK, 256>>>(norm, wg + (size_t)lo * Dn * NEn,
                                  raw, idx1, idx2, keep, g1, g2, ka, kbb);
        loss_sum_kernel<<<Bn * NEn, 256>>>(raw, idx1, rawsum, cnt1);
        slots_kernel<<<1, 256>>>(idx1, idx2, keep, slot1, slot2, rawsum, cnt1, lossp);
        scatter_kernel<<<TOK, 128>>>(normh, norml, slot1, slot2, xeh, xel);
        mma_gemm<<<dim3(16, 5, 8), 256, MGSMEM>>>(
            xeh, xel,
            whi + MW1_OFF + (long long)lo * 16777216,
            wlo + MW1_OFF + (long long)lo * 16777216,
            (float*)0, hidh, hidl, NILF, NILF, NILF,
            Bn * CAPn, MOEHn, 1024, sXE, 2097152LL, sHID, 2);
        mma_gemm<<<dim3(8, 5, 8), 256, MGSMEM>>>(
            hidh, hidl,
            whi + MW2_OFF + (long long)lo * 16777216,
            wlo + MW2_OFF + (long long)lo * 16777216,
            ye, NILB, NILB, NILF, NILF, NILF,
            Bn * CAPn, 1024, 2048, sHID, 2097152LL, sXE, 0);
        combine_kernel<<<TOK, 256>>>(ye, slot1, slot2, g1, g2, xout);
    };

    attn_tail(0);               // layer-0 rmsnorm/qkv/flash issued above
    mlp_layer(0, 1);
    moe_layer(0, 2, k1a, k1b);
    mlp_layer(1, 3);
    attn_layer(1, 4);
    moe_layer(1, 5, k2a, k2b);
    attn_layer(2, 6);
    mlp_layer(2, 7);
}

// round 15
// speedup vs baseline: 2.0966x; 1.0082x over previous
#include <cuda_runtime.h>
#include <cuda_bf16.h>
#include <stdint.h>
#include <math.h>

#define Bn 4
#define Nn 1024
#define Dn 1024
#define NHn 16
#define HDn 64
#define FFHn 2816
#define MOEHn 2048
#define NEn 8
#define CAPn 160
#define TOK (Bn*Nn)
#define NSLOT (NEn*Bn*CAPn)

#define QKV_OFF 0LL
#define WO_OFF  9437184LL
#define W1_OFF  12582912LL
#define W3_OFF  21233664LL
#define W2_OFF  29884416LL
#define MW1_OFF 38535168LL
#define MW2_OFF 72089600LL
#define WTOTAL  105644032LL

typedef unsigned long long u64t;

static __device__ float g_norm[TOK*Dn];
static __device__ __nv_bfloat16 g_normh[TOK*Dn], g_norml[TOK*Dn];
static __device__ __nv_bfloat16 g_bigh[TOK*3*Dn], g_bigl[TOK*3*Dn];
static __device__ __nv_bfloat16 g_attnh[TOK*Dn], g_attnl[TOK*Dn];
static __device__ float g_h1[TOK*FFHn];
static __device__ __nv_bfloat16 g_hidh[TOK*FFHn], g_hidl[TOK*FFHn];
static __device__ __nv_bfloat16 g_xeh[NSLOT*Dn], g_xel[NSLOT*Dn];
static __device__ float g_ye[NSLOT*Dn];
static __device__ float g_raw [TOK*NEn];
static __device__ int   g_idx1[TOK], g_idx2[TOK], g_keep[TOK];
static __device__ int   g_slot1[TOK], g_slot2[TOK];
static __device__ float g_g1[TOK], g_g2[TOK];
static __device__ float g_rawsum[Bn*NEn], g_cnt1[Bn*NEn];
static __device__ float g_lossbuf[1];
static __device__ __nv_bfloat16 g_whi[WTOTAL];
static __device__ __nv_bfloat16 g_wlo[WTOTAL];

__host__ __device__ __forceinline__ void threefry2x32(unsigned k0, unsigned k1,
                                                      unsigned& x0, unsigned& x1)
{
    unsigned ks2 = k0 ^ k1 ^ 0x1BD11BDAu;
    x0 += k0; x1 += k1;
#define TFR(r) { x0 += x1; x1 = (x1<<(r))|(x1>>(32-(r))); x1 ^= x0; }
    TFR(13) TFR(15) TFR(26) TFR(6)
    x0 += k1;  x1 += ks2 + 1u;
    TFR(17) TFR(29) TFR(16) TFR(24)
    x0 += ks2; x1 += k0 + 2u;
    TFR(13) TFR(15) TFR(26) TFR(6)
    x0 += k0;  x1 += k1 + 3u;
    TFR(17) TFR(29) TFR(16) TFR(24)
    x0 += k1;  x1 += ks2 + 4u;
    TFR(13) TFR(15) TFR(26) TFR(6)
    x0 += ks2; x1 += k0 + 5u;
#undef TFR
}

__global__ void wprep_kernel(const float* __restrict__ W, __nv_bfloat16* __restrict__ hi,
                             __nv_bfloat16* __restrict__ lo, int K, int N,
                             long long sW, long long sO)
{
    __shared__ float t[32][33];
    W  += (long long)blockIdx.z * sW;
    hi += (long long)blockIdx.z * sO;
    lo += (long long)blockIdx.z * sO;
    int n0 = blockIdx.x * 32, k0 = blockIdx.y * 32;
#pragma unroll
    for (int j = 0; j < 4; j++)
        t[threadIdx.y + j*8][threadIdx.x] =
            W[(size_t)(k0 + threadIdx.y + j*8) * N + n0 + threadIdx.x];
    __syncthreads();
#pragma unroll
    for (int j = 0; j < 4; j++) {
        int n = n0 + threadIdx.y + j*8, k = k0 + threadIdx.x;
        float v = t[threadIdx.x][threadIdx.y + j*8];
        __nv_bfloat16 h = __float2bfloat16(v);
        hi[(size_t)n * K + k] = h;
        lo[(size_t)n * K + k] = __float2bfloat16(v - __bfloat162float(h));
    }
}

__device__ __forceinline__ uint32_t smem_u32(const void* p) {
    uint32_t a;
    asm("{ .reg .u64 t; cvta.to.shared.u64 t, %1; cvt.u32.u64 %0, t; }"
        : "=r"(a) : "l"(p));
    return a;
}
__device__ __forceinline__ void split2(float a, float b, uint32_t& hi, uint32_t& lo) {
    __nv_bfloat16 ha = __float2bfloat16(a), hb = __float2bfloat16(b);
    __nv_bfloat16 la = __float2bfloat16(a - __bfloat162float(ha));
    __nv_bfloat16 lb = __float2bfloat16(b - __bfloat162float(hb));
    hi = (uint32_t)__bfloat16_as_ushort(ha) | ((uint32_t)__bfloat16_as_ushort(hb) << 16);
    lo = (uint32_t)__bfloat16_as_ushort(la) | ((uint32_t)__bfloat16_as_ushort(lb) << 16);
}
__device__ __forceinline__ float gelu_f(float v) {
    return 0.5f * v * (1.0f + erff(v * 0.70710678118654752f));
}
__device__ __forceinline__ float silu_f(float v) {
    return v / (1.f + expf(-v));
}

#define LDSM4(r0,r1,r2,r3,addr) asm volatile( \
    "ldmatrix.sync.aligned.m8n8.x4.shared.b16 {%0,%1,%2,%3}, [%4];" \
    : "=r"(r0),"=r"(r1),"=r"(r2),"=r"(r3) : "r"(addr))

#define LDSM4T(r0,r1,r2,r3,addr) asm volatile( \
    "ldmatrix.sync.aligned.m8n8.x4.trans.shared.b16 {%0,%1,%2,%3}, [%4];" \
    : "=r"(r0),"=r"(r1),"=r"(r2),"=r"(r3) : "r"(addr))

#define MMA16816(c,a0,a1,a2,a3,b0,b1) asm volatile( \
    "mma.sync.aligned.m16n8k16.row.col.f32.bf16.bf16.f32 " \
    "{%0,%1,%2,%3}, {%4,%5,%6,%7}, {%8,%9}, {%0,%1,%2,%3};" \
    : "+f"((c)[0]),"+f"((c)[1]),"+f"((c)[2]),"+f"((c)[3]) \
    : "r"(a0),"r"(a1),"r"(a2),"r"(a3),"r"(b0),"r"(b1))

// ---------- HMMA GEMM: bf16x3 split, 2-stage cp.async, single-sync mainloop ----------
// op0: Cf=v  op1: Cf+=v  op2: split(gelu(v))  op3: split(silu(Aux)*v)
// op4: split(rope(v)) for cols<2048 else split(v) -> Chi/Clo
#define ROWE 40
#define TILEB 10240u
#define STGB  40960u
#define MGSMEM 81920
__global__ void __launch_bounds__(256, 2) mma_gemm(
    const __nv_bfloat16* __restrict__ Ah, const __nv_bfloat16* __restrict__ Al,
    const __nv_bfloat16* __restrict__ Bh, const __nv_bfloat16* __restrict__ Bl,
    float* __restrict__ Cf, __nv_bfloat16* __restrict__ Chi,
    __nv_bfloat16* __restrict__ Clo, const float* __restrict__ Aux,
    const float* __restrict__ Cos, const float* __restrict__ Sin,
    int M, int N, int K, long long sA, long long sB, long long sC, int op)
{
    extern __shared__ char smraw[];
    Ah += (long long)blockIdx.z * sA;  Al += (long long)blockIdx.z * sA;
    Bh += (long long)blockIdx.z * sB;  Bl += (long long)blockIdx.z * sB;
    if (Cf)  Cf  += (long long)blockIdx.z * sC;
    if (Chi) { Chi += (long long)blockIdx.z * sC; Clo += (long long)blockIdx.z * sC; }
    if (Aux) Aux += (long long)blockIdx.z * sC;
    const int tid = threadIdx.x, lane = tid & 31, w = tid >> 5;
    const int warp_m = w & 3, warp_n = w >> 2;
    const int row0 = blockIdx.y << 7, col0 = blockIdx.x << 7;
    const uint32_t sb = smem_u32(smraw);

    const __nv_bfloat16* Ahg = Ah + (size_t)row0 * K;
    const __nv_bfloat16* Alg = Al + (size_t)row0 * K;
    const __nv_bfloat16* Bhg = Bh + (size_t)col0 * K;
    const __nv_bfloat16* Blg = Bl + (size_t)col0 * K;
    const int S = K >> 5;

    float acc[2][8][4];
#pragma unroll
    for (int mt = 0; mt < 2; mt++)
#pragma unroll
        for (int nt = 0; nt < 8; nt++)
#pragma unroll
            for (int j = 0; j < 4; j++) acc[mt][nt][j] = 0.f;

    auto issue = [&](int s) {
        if (s < S) {
            uint32_t base = sb + (uint32_t)(s & 1) * STGB;
            int k0e = s << 5;
            const __nv_bfloat16* gsrc[4] = {Ahg, Alg, Bhg, Blg};
#pragma unroll
            for (int t4 = 0; t4 < 4; t4++) {
                const __nv_bfloat16* gp = gsrc[t4] + k0e;
                uint32_t tb = base + (uint32_t)t4 * TILEB;
#pragma unroll
                for (int i = 0; i < 2; i++) {
                    int c = (i << 8) + tid, row = c >> 2, q = c & 3;
                    uint32_t d = tb + (uint32_t)(row * (ROWE*2) + q * 16);
                    const void* sp = (const char*)(gp + (size_t)row * K) + (q << 4);
                    asm volatile("cp.async.cg.shared.global [%0], [%1], 16;"
                                 :: "r"(d), "l"(sp));
                }
            }
        }
        asm volatile("cp.async.commit_group;" ::: "memory");
    };

    const uint32_t a_off = (uint32_t)((lane & 15) * ROWE + ((lane >> 4) << 3)) * 2u;
    const uint32_t b_off = (uint32_t)(((lane & 7) + ((lane >> 4) << 3)) * ROWE
                                      + (((lane >> 3) & 1) << 3)) * 2u;
    const uint32_t a_mrow = (uint32_t)(warp_m * 32) * (ROWE * 2u);
    const uint32_t b_nrow = (uint32_t)(warp_n * 64) * (ROWE * 2u);

    auto compute = [&](uint32_t base) {
#pragma unroll
        for (int k16 = 0; k16 < 2; k16++) {
            uint32_t kb = (uint32_t)(k16 << 5);
            uint32_t b[4][4];
            uint32_t ah[2][4], al[2][4];
#pragma unroll
            for (int ntp = 0; ntp < 4; ntp++) {
                uint32_t bd = base + 2u * TILEB + b_nrow
                              + (uint32_t)(ntp * 16) * (ROWE*2u) + b_off + kb;
                LDSM4(b[ntp][0], b[ntp][1], b[ntp][2], b[ntp][3], bd);
            }
#pragma unroll
            for (int mt = 0; mt < 2; mt++) {
                uint32_t ad = base + a_mrow + (uint32_t)(mt * 16) * (ROWE*2u)
                              + a_off + kb;
                LDSM4(ah[mt][0], ah[mt][1], ah[mt][2], ah[mt][3], ad);
                LDSM4(al[mt][0], al[mt][1], al[mt][2], al[mt][3], ad + TILEB);
            }
#pragma unroll
            for (int mt = 0; mt < 2; mt++)
#pragma unroll
                for (int nt = 0; nt < 8; nt++) {
                    int ntp = nt >> 1, hi = (nt & 1) << 1;
                    MMA16816(acc[mt][nt], ah[mt][0], ah[mt][1], ah[mt][2], ah[mt][3],
                             b[ntp][hi], b[ntp][hi + 1]);
                }
#pragma unroll
            for (int mt = 0; mt < 2; mt++)
#pragma unroll
                for (int nt = 0; nt < 8; nt++) {
                    int ntp = nt >> 1, hi = (nt & 1) << 1;
                    MMA16816(acc[mt][nt], al[mt][0], al[mt][1], al[mt][2], al[mt][3],
                             b[ntp][hi], b[ntp][hi + 1]);
                }
#pragma unroll
            for (int ntp = 0; ntp < 4; ntp++) {
                uint32_t bd = base + 3u * TILEB + b_nrow
                              + (uint32_t)(ntp * 16) * (ROWE*2u) + b_off + kb;
                LDSM4(b[ntp][0], b[ntp][1], b[ntp][2], b[ntp][3], bd);
            }
#pragma unroll
            for (int mt = 0; mt < 2; mt++)
#pragma unroll
                for (int nt = 0; nt < 8; nt++) {
                    int ntp = nt >> 1, hi = (nt & 1) << 1;
                    MMA16816(acc[mt][nt], ah[mt][0], ah[mt][1], ah[mt][2], ah[mt][3],
                             b[ntp][hi], b[ntp][hi + 1]);
                }
        }
    };

    // single-sync mainloop: one barrier per K-step, load s+1 overlaps compute s
    issue(0);
    for (int s = 0; s < S; s++) {
        asm volatile("cp.async.wait_group 0;" ::: "memory");
        __syncthreads();
        issue(s + 1);
        compute(sb + (uint32_t)(s & 1) * STGB);
    }

    const int rbase = row0 + warp_m * 32 + (lane >> 2);
    const int cbase = col0 + warp_n * 64 + ((lane & 3) << 1);
#pragma unroll
    for (int mt = 0; mt < 2; mt++) {
#pragma unroll
        for (int nt = 0; nt < 8; nt++) {
#pragma unroll
            for (int half = 0; half < 2; half++) {
                int r = rbase + mt * 16 + half * 8;
                int c = cbase + nt * 8;
                size_t idx = (size_t)r * N + c;
                float v0 = acc[mt][nt][half * 2], v1 = acc[mt][nt][half * 2 + 1];
                if (op == 0) {
                    *(float2*)(Cf + idx) = make_float2(v0, v1);
                } else if (op == 1) {
                    float2 old = *(const float2*)(Cf + idx);
                    *(float2*)(Cf + idx) = make_float2(v0 + old.x, v1 + old.y);
                } else if (op == 4) {
                    float o0 = v0, o1 = v1;
                    if (c < 2048) {
                        int n = r & (Nn - 1);
                        int i = (c & 63) >> 1;
                        float co = Cos[n * 32 + i], si = Sin[n * 32 + i];
                        o0 = v0 * co - v1 * si;
                        o1 = v0 * si + v1 * co;
                    }
                    uint32_t h_, l_;
                    split2(o0, o1, h_, l_);
                    *(uint32_t*)(Chi + idx) = h_;
                    *(uint32_t*)(Clo + idx) = l_;
                } else {
                    float p0, p1;
                    if (op == 2) { p0 = gelu_f(v0); p1 = gelu_f(v1); }
                    else {
                        float2 a2 = *(const float2*)(Aux + idx);
                        p0 = silu_f(a2.x) * v0; p1 = silu_f(a2.y) * v1;
                    }
                    uint32_t h_, l_;
                    split2(p0, p1, h_, l_);
                    *(uint32_t*)(Chi + idx) = h_;
                    *(uint32_t*)(Clo + idx) = l_;
                }
            }
        }
    }
}

__global__ void rmsnorm_kernel(const float* __restrict__ x, const float* __restrict__ w,
                               float* __restrict__ out, __nv_bfloat16* __restrict__ oh,
                               __nv_bfloat16* __restrict__ ol)
{
    __shared__ float red[256];
    int t = blockIdx.x;
    const float* xr = x + (size_t)t * Dn;
    float ss = 0.f;
    for (int i = threadIdx.x; i < Dn; i += 256) { float v = xr[i]; ss += v * v; }
    red[threadIdx.x] = ss; __syncthreads();
    for (int s = 128; s > 0; s >>= 1) {
        if (threadIdx.x < s) red[threadIdx.x] += red[threadIdx.x + s];
        __syncthreads();
    }
    float inv = rsqrtf(red[0] * (1.0f / Dn) + 1e-5f);
    float* orow = out + (size_t)t * Dn;
    __nv_bfloat16* ohr = oh + (size_t)t * Dn;
    __nv_bfloat16* olr = ol + (size_t)t * Dn;
    for (int i = threadIdx.x * 2; i < Dn; i += 512) {
        float a = xr[i] * inv * w[i], b = xr[i+1] * inv * w[i+1];
        orow[i] = a; orow[i+1] = b;
        uint32_t h_, l_;
        split2(a, b, h_, l_);
        *(uint32_t*)(ohr + i) = h_;
        *(uint32_t*)(olr + i) = l_;
    }
}

// ---------- HMMA flash attention: bf16 hi/lo inputs, trans-ldmatrix V ----------
#define FROWE 72
#define FSM 61440
__global__ void __launch_bounds__(128, 3) flash_kernel(
    const __nv_bfloat16* __restrict__ qkvh, const __nv_bfloat16* __restrict__ qkvl,
    __nv_bfloat16* __restrict__ outh, __nv_bfloat16* __restrict__ outl)
{
    extern __shared__ char smf[];
    const uint32_t sb = smem_u32(smf);
    const uint32_t Qh = sb, Ql = sb + 10240u, Kh = sb + 20480u, Kl = sb + 30720u,
                   Vh = sb + 40960u, Vl = sb + 51200u;
    const int qt = (int)gridDim.x - 1 - (int)blockIdx.x;
    const int bh = blockIdx.y;
    const int b = bh >> 4, h = bh & 15;
    const int tid = threadIdx.x, lane = tid & 31, w = tid >> 5;
    const size_t base = (size_t)(b * Nn) * 3072 + h * 64;
    const int q0 = qt * 64;
    const int r0 = lane >> 2, c2 = (lane & 3) << 1;

    for (int i = tid; i < 512; i += 128) {
        int row = i >> 3, q = i & 7;
        uint32_t d = (uint32_t)(row * (FROWE*2) + q * 16);
        size_t go = base + (size_t)(q0 + row) * 3072 + q * 8;
        asm volatile("cp.async.cg.shared.global [%0], [%1], 16;"
                     :: "r"(Qh + d), "l"((const void*)(qkvh + go)));
        asm volatile("cp.async.cg.shared.global [%0], [%1], 16;"
                     :: "r"(Ql + d), "l"((const void*)(qkvl + go)));
    }
    asm volatile("cp.async.commit_group;" ::: "memory");

    float acc_o[8][4];
#pragma unroll
    for (int nt = 0; nt < 8; nt++)
#pragma unroll
        for (int j = 0; j < 4; j++) acc_o[nt][j] = 0.f;
    float m0 = -1e30f, m1 = -1e30f, l0s = 0.f, l1s = 0.f;

    const uint32_t a_off = (uint32_t)((lane & 15) * FROWE + ((lane >> 4) << 3)) * 2u
                           + (uint32_t)(w * 16 * FROWE) * 2u;
    const uint32_t b_off = (uint32_t)(((lane & 7) + ((lane >> 4) << 3)) * FROWE
                                      + (((lane >> 3) & 1) << 3)) * 2u;
    const uint32_t v_off = (uint32_t)((((lane & 7) + (((lane >> 3) & 1) << 3)) * FROWE
                                      + ((lane >> 4) << 3)) * 2);

    for (int kt = 0; kt <= qt; kt++) {
        int k0 = kt * 64;
        for (int i = tid; i < 512; i += 128) {
            int row = i >> 3, q = i & 7;
            uint32_t d = (uint32_t)(row * (FROWE*2) + q * 16);
            size_t go = base + (size_t)(k0 + row) * 3072 + q * 8;
            asm volatile("cp.async.cg.shared.global [%0], [%1], 16;"
                         :: "r"(Kh + d), "l"((const void*)(qkvh + go + 1024)));
            asm volatile("cp.async.cg.shared.global [%0], [%1], 16;"
                         :: "r"(Kl + d), "l"((const void*)(qkvl + go + 1024)));
            asm volatile("cp.async.cg.shared.global [%0], [%1], 16;"
                         :: "r"(Vh + d), "l"((const void*)(qkvh + go + 2048)));
            asm volatile("cp.async.cg.shared.global [%0], [%1], 16;"
                         :: "r"(Vl + d), "l"((const void*)(qkvl + go + 2048)));
        }
        asm volatile("cp.async.commit_group;" ::: "memory");
        asm volatile("cp.async.wait_group 0;" ::: "memory");
        __syncthreads();

        float s[8][4];
#pragma unroll
        for (int nt = 0; nt < 8; nt++)
#pragma unroll
            for (int j = 0; j < 4; j++) s[nt][j] = 0.f;
#pragma unroll
        for (int kk = 0; kk < 4; kk++) {
            uint32_t kb = (uint32_t)(kk << 5);
            uint32_t qh[4], ql[4], kf[4][4];
            LDSM4(qh[0], qh[1], qh[2], qh[3], Qh + a_off + kb);
            LDSM4(ql[0], ql[1], ql[2], ql[3], Ql + a_off + kb);
#pragma unroll
            for (int ntp = 0; ntp < 4; ntp++)
                LDSM4(kf[ntp][0], kf[ntp][1], kf[ntp][2], kf[ntp][3],
                      Kh + b_off + (uint32_t)(ntp * 16) * (FROWE*2u) + kb);
#pragma unroll
            for (int nt = 0; nt < 8; nt++) {
                int ntp = nt >> 1, hi = (nt & 1) << 1;
                MMA16816(s[nt], qh[0], qh[1], qh[2], qh[3], kf[ntp][hi], kf[ntp][hi+1]);
            }
#pragma unroll
            for (int nt = 0; nt < 8; nt++) {
                int ntp = nt >> 1, hi = (nt & 1) << 1;
                MMA16816(s[nt], ql[0], ql[1], ql[2], ql[3], kf[ntp][hi], kf[ntp][hi+1]);
            }
#pragma unroll
            for (int ntp = 0; ntp < 4; ntp++)
                LDSM4(kf[ntp][0], kf[ntp][1], kf[ntp][2], kf[ntp][3],
                      Kl + b_off + (uint32_t)(ntp * 16) * (FROWE*2u) + kb);
#pragma unroll
            for (int nt = 0; nt < 8; nt++) {
                int ntp = nt >> 1, hi = (nt & 1) << 1;
                MMA16816(s[nt], qh[0], qh[1], qh[2], qh[3], kf[ntp][hi], kf[ntp][hi+1]);
            }
        }

        int row0g = q0 + w * 16 + r0, row1g = row0g + 8;
        float mx0 = -1e30f, mx1 = -1e30f;
#pragma unroll
        for (int nt = 0; nt < 8; nt++) {
            int cg = k0 + nt * 8 + c2;
#pragma unroll
            for (int j = 0; j < 4; j++) s[nt][j] *= 0.125f;
            if (kt == qt) {
                if (cg     > row0g) s[nt][0] = -1e30f;
                if (cg + 1 > row0g) s[nt][1] = -1e30f;
                if (cg     > row1g) s[nt][2] = -1e30f;
                if (cg + 1 > row1g) s[nt][3] = -1e30f;
            }
            mx0 = fmaxf(mx0, fmaxf(s[nt][0], s[nt][1]));
            mx1 = fmaxf(mx1, fmaxf(s[nt][2], s[nt][3]));
        }
        mx0 = fmaxf(mx0, __shfl_xor_sync(0xffffffffu, mx0, 1));
        mx0 = fmaxf(mx0, __shfl_xor_sync(0xffffffffu, mx0, 2));
        mx1 = fmaxf(mx1, __shfl_xor_sync(0xffffffffu, mx1, 1));
        mx1 = fmaxf(mx1, __shfl_xor_sync(0xffffffffu, mx1, 2));
        float mn0 = fmaxf(m0, mx0), mn1 = fmaxf(m1, mx1);
        float cr0 = expf(m0 - mn0), cr1 = expf(m1 - mn1);
        float ps0 = 0.f, ps1 = 0.f;
#pragma unroll
        for (int nt = 0; nt < 8; nt++) {
            s[nt][0] = expf(s[nt][0] - mn0); ps0 += s[nt][0];
            s[nt][1] = expf(s[nt][1] - mn0); ps0 += s[nt][1];
            s[nt][2] = expf(s[nt][2] - mn1); ps1 += s[nt][2];
            s[nt][3] = expf(s[nt][3] - mn1); ps1 += s[nt][3];
        }
        ps0 += __shfl_xor_sync(0xffffffffu, ps0, 1);
        ps0 += __shfl_xor_sync(0xffffffffu, ps0, 2);
        ps1 += __shfl_xor_sync(0xffffffffu, ps1, 1);
        ps1 += __shfl_xor_sync(0xffffffffu, ps1, 2);
        l0s = l0s * cr0 + ps0;
        l1s = l1s * cr1 + ps1;
        m0 = mn0; m1 = mn1;
#pragma unroll
        for (int nt = 0; nt < 8; nt++) {
            acc_o[nt][0] *= cr0; acc_o[nt][1] *= cr0;
            acc_o[nt][2] *= cr1; acc_o[nt][3] *= cr1;
        }

#pragma unroll
        for (int kk = 0; kk < 4; kk++) {
            uint32_t krow = (uint32_t)(kk * 16) * (FROWE*2u);
            uint32_t ph[4], pl[4], vf[4][4];
            split2(s[2*kk][0],   s[2*kk][1],   ph[0], pl[0]);
            split2(s[2*kk][2],   s[2*kk][3],   ph[1], pl[1]);
            split2(s[2*kk+1][0], s[2*kk+1][1], ph[2], pl[2]);
            split2(s[2*kk+1][2], s[2*kk+1][3], ph[3], pl[3]);
#pragma unroll
            for (int ntp = 0; ntp < 4; ntp++)
                LDSM4T(vf[ntp][0], vf[ntp][1], vf[ntp][2], vf[ntp][3],
                       Vh + v_off + krow + (uint32_t)(ntp * 16) * 2u);
#pragma unroll
            for (int nt = 0; nt < 8; nt++) {
                int ntp = nt >> 1, hi = (nt & 1) << 1;
                MMA16816(acc_o[nt], ph[0], ph[1], ph[2], ph[3], vf[ntp][hi], vf[ntp][hi+1]);
            }
#pragma unroll
            for (int nt = 0; nt < 8; nt++) {
                int ntp = nt >> 1, hi = (nt & 1) << 1;
                MMA16816(acc_o[nt], pl[0], pl[1], pl[2], pl[3], vf[ntp][hi], vf[ntp][hi+1]);
            }
#pragma unroll
            for (int ntp = 0; ntp < 4; ntp++)
                LDSM4T(vf[ntp][0], vf[ntp][1], vf[ntp][2], vf[ntp][3],
                       Vl + v_off + krow + (uint32_t)(ntp * 16) * 2u);
#pragma unroll
            for (int nt = 0; nt < 8; nt++) {
                int ntp = nt >> 1, hi = (nt & 1) << 1;
                MMA16816(acc_o[nt], ph[0], ph[1], ph[2], ph[3], vf[ntp][hi], vf[ntp][hi+1]);
            }
        }
        __syncthreads();
    }

    float inv0 = 1.f / l0s, inv1 = 1.f / l1s;
    size_t ob0 = ((size_t)(b * Nn + q0 + w * 16 + r0)) * Dn + h * HDn;
    size_t ob1 = ob0 + (size_t)8 * Dn;
#pragma unroll
    for (int nt = 0; nt < 8; nt++) {
        int cc = nt * 8 + c2;
        uint32_t hh, llv;
        split2(acc_o[nt][0] * inv0, acc_o[nt][1] * inv0, hh, llv);
        *(uint32_t*)(outh + ob0 + cc) = hh;
        *(uint32_t*)(outl + ob0 + cc) = llv;
        split2(acc_o[nt][2] * inv1, acc_o[nt][3] * inv1, hh, llv);
        *(uint32_t*)(outh + ob1 + cc) = hh;
        *(uint32_t*)(outl + ob1 + cc) = llv;
    }
}

__global__ void gate_kernel(const float* __restrict__ xn, const float* __restrict__ wg,
                            float* __restrict__ raw, int* __restrict__ idx1,
                            int* __restrict__ idx2, int* __restrict__ keep,
                            float* __restrict__ g1o, float* __restrict__ g2o,
                            unsigned key0, unsigned key1)
{
    __shared__ float red[8 * 256];
    int t = blockIdx.x;
    const float* xr = xn + (size_t)t * Dn;
    float acc[8] = {0,0,0,0,0,0,0,0};
    for (int i = threadIdx.x; i < Dn; i += 256) {
        float v = xr[i];
        const float* wr = wg + (size_t)i * NEn;
#pragma unroll
        for (int e = 0; e < 8; e++) acc[e] += v * wr[e];
    }
#pragma unroll
    for (int e = 0; e < 8; e++) red[e * 256 + threadIdx.x] = acc[e];
    __syncthreads();
    for (int s = 128; s > 0; s >>= 1) {
        if (threadIdx.x < s) {
#pragma unroll
            for (int e = 0; e < 8; e++)
                red[e * 256 + threadIdx.x] += red[e * 256 + threadIdx.x + s];
        }
        __syncthreads();
    }
    if (threadIdx.x == 0) {
        float p[8];
        float mx = red[0];
#pragma unroll
        for (int e = 1; e < 8; e++) mx = fmaxf(mx, red[e * 256]);
        float sum = 0.f;
#pragma unroll
        for (int e = 0; e < 8; e++) { p[e] = expf(red[e * 256] - mx); sum += p[e]; }
#pragma unroll
        for (int e = 0; e < 8; e++) p[e] /= sum;
        int i1 = 0; float b1 = p[0];
#pragma unroll
        for (int e = 1; e < 8; e++) if (p[e] > b1) { b1 = p[e]; i1 = e; }
        int i2 = -1; float b2 = -1.f;
#pragma unroll
        for (int e = 0; e < 8; e++) if (e != i1 && p[e] > b2) { b2 = p[e]; i2 = e; }
        float denom = b1 + b2 + 1e-9f;
        float g1 = b1 / denom, g2 = b2 / denom;
        unsigned x0 = 0u, x1 = (unsigned)t;
        threefry2x32(key0, key1, x0, x1);
        unsigned bits = x0 ^ x1;
        float u = __uint_as_float((bits >> 9) | 0x3F800000u) - 1.0f;
        int kp = (u < (g2 / 0.2f)) ? 1 : 0;
#pragma unroll
        for (int e = 0; e < 8; e++) raw[t * NEn + e] = p[e];
        idx1[t] = i1; idx2[t] = i2; keep[t] = kp; g1o[t] = g1; g2o[t] = g2;
    }
}

__global__ void loss_sum_kernel(const float* __restrict__ raw, const int* __restrict__ idx1,
                                float* __restrict__ rawsum, float* __restrict__ cnt1)
{
    __shared__ float r1[256], r2[256];
    int be = blockIdx.x, b = be >> 3, e = be & 7;
    float s1 = 0.f, s2 = 0.f;
    for (int n = threadIdx.x; n < Nn; n += 256) {
        int t = b * Nn + n;
        s1 += raw[t * NEn + e];
        s2 += (idx1[t] == e) ? 1.f : 0.f;
    }
    r1[threadIdx.x] = s1; r2[threadIdx.x] = s2; __syncthreads();
    for (int s = 128; s > 0; s >>= 1) {
        if (threadIdx.x < s) {
            r1[threadIdx.x] += r1[threadIdx.x + s];
            r2[threadIdx.x] += r2[threadIdx.x + s];
        }
        __syncthreads();
    }
    if (threadIdx.x == 0) { rawsum[be] = r1[0]; cnt1[be] = r2[0]; }
}

__global__ void slots_kernel(const int* __restrict__ idx1, const int* __restrict__ idx2,
                             const int* __restrict__ keep, int* __restrict__ slot1,
                             int* __restrict__ slot2, const float* __restrict__ rawsum,
                             const float* __restrict__ cnt1, float* __restrict__ loss_out)
{
    __shared__ char si1[TOK], si2[TOK], skp[TOK];
    __shared__ float lred[32];
    int tid = threadIdx.x;
    for (int i = tid; i < TOK; i += 256) {
        si1[i] = (char)idx1[i]; si2[i] = (char)idx2[i]; skp[i] = (char)keep[i];
        slot1[i] = -1; slot2[i] = -1;
    }
    __syncthreads();
    if (tid < 32) {
        int b = tid >> 3, e = tid & 7;
        int base = (e * Bn + b) * CAPn;
        int c = 0;
        for (int n = 0; n < Nn; n++) {
            int t = b * Nn + n;
            if (si1[t] == e) { if (c < CAPn) slot1[t] = base + c; c++; }
        }
        int m1c = c < CAPn ? c : CAPn;
        int c2 = 0;
        for (int n = 0; n < Nn; n++) {
            int t = b * Nn + n;
            if (si2[t] == e && skp[t]) {
                int pos = m1c + c2; c2++;
                if (pos < CAPn) slot2[t] = base + pos;
            }
        }
        lred[tid] = rawsum[tid] * (1.f / Nn) * cnt1[tid] * (1.f / Nn);
    }
    __syncthreads();
    if (tid == 0) {
        float s = 0.f;
        for (int i = 0; i < 32; i++) s += lred[i];
        *loss_out += s * 0.02f;
    }
}

__global__ void scatter_kernel(const __nv_bfloat16* __restrict__ xnh,
                               const __nv_bfloat16* __restrict__ xnl,
                               const int* __restrict__ slot1, const int* __restrict__ slot2,
                               __nv_bfloat16* __restrict__ xeh, __nv_bfloat16* __restrict__ xel)
{
    int t = blockIdx.x;
    int s1 = slot1[t], s2 = slot2[t];
    if (s1 < 0 && s2 < 0) return;
    uint4 vh = ((const uint4*)(xnh + (size_t)t * Dn))[threadIdx.x];
    uint4 vl = ((const uint4*)(xnl + (size_t)t * Dn))[threadIdx.x];
    if (s1 >= 0) {
        ((uint4*)(xeh + (size_t)s1 * Dn))[threadIdx.x] = vh;
        ((uint4*)(xel + (size_t)s1 * Dn))[threadIdx.x] = vl;
    }
    if (s2 >= 0) {
        ((uint4*)(xeh + (size_t)s2 * Dn))[threadIdx.x] = vh;
        ((uint4*)(xel + (size_t)s2 * Dn))[threadIdx.x] = vl;
    }
}

__global__ void combine_kernel(const float* __restrict__ ye, const int* __restrict__ slot1,
                               const int* __restrict__ slot2, const float* __restrict__ g1,
                               const float* __restrict__ g2, float* __restrict__ x)
{
    int t = blockIdx.x;
    int s1 = slot1[t], s2 = slot2[t];
    if (s1 < 0 && s2 < 0) return;
    float a = (s1 >= 0) ? g1[t] : 0.f;
    float b = (s2 >= 0) ? g2[t] : 0.f;
    float4* xr = (float4*)(x + (size_t)t * Dn);
    float4 v = xr[threadIdx.x];
    if (s1 >= 0) {
        float4 w = ((const float4*)(ye + (size_t)s1 * Dn))[threadIdx.x];
        v.x += a * w.x; v.y += a * w.y; v.z += a * w.z; v.w += a * w.w;
    }
    if (s2 >= 0) {
        float4 w = ((const float4*)(ye + (size_t)s2 * Dn))[threadIdx.x];
        v.x += b * w.x; v.y += b * w.y; v.z += b * w.z; v.w += b * w.w;
    }
    xr[threadIdx.x] = v;
}

extern "C" void kernel_launch(void* const* d_in, const int* in_sizes, int n_in,
                              void* d_out, int out_size)
{
    const float* x    = (const float*)d_in[0];
    const float* cosb = (const float*)d_in[1];
    const float* sinb = (const float*)d_in[2];
    const float* ln   = (const float*)d_in[3];
    const float* wqkv = (const float*)d_in[4];
    const float* wo   = (const float*)d_in[5];
    const float* w1   = (const float*)d_in[6];
    const float* w2   = (const float*)d_in[7];
    const float* w3   = (const float*)d_in[8];
    const float* wg   = (const float*)d_in[9];
    const float* mw1  = (const float*)d_in[10];
    const float* mw2  = (const float*)d_in[11];
    float* xout = (float*)d_out;

    void* p;
    cudaGetSymbolAddress(&p, g_norm);  float* norm  = (float*)p;
    cudaGetSymbolAddress(&p, g_normh); __nv_bfloat16* normh = (__nv_bfloat16*)p;
    cudaGetSymbolAddress(&p, g_norml); __nv_bfloat16* norml = (__nv_bfloat16*)p;
    cudaGetSymbolAddress(&p, g_bigh);  __nv_bfloat16* bigh = (__nv_bfloat16*)p;
    cudaGetSymbolAddress(&p, g_bigl);  __nv_bfloat16* bigl = (__nv_bfloat16*)p;
    cudaGetSymbolAddress(&p, g_attnh); __nv_bfloat16* attnh = (__nv_bfloat16*)p;
    cudaGetSymbolAddress(&p, g_attnl); __nv_bfloat16* attnl = (__nv_bfloat16*)p;
    cudaGetSymbolAddress(&p, g_h1);    float* h1    = (float*)p;
    cudaGetSymbolAddress(&p, g_hidh);  __nv_bfloat16* hidh = (__nv_bfloat16*)p;
    cudaGetSymbolAddress(&p, g_hidl);  __nv_bfloat16* hidl = (__nv_bfloat16*)p;
    cudaGetSymbolAddress(&p, g_xeh);   __nv_bfloat16* xeh = (__nv_bfloat16*)p;
    cudaGetSymbolAddress(&p, g_xel);   __nv_bfloat16* xel = (__nv_bfloat16*)p;
    cudaGetSymbolAddress(&p, g_ye);    float* ye    = (float*)p;
    cudaGetSymbolAddress(&p, g_raw);   float* raw   = (float*)p;
    cudaGetSymbolAddress(&p, g_idx1);  int* idx1    = (int*)p;
    cudaGetSymbolAddress(&p, g_idx2);  int* idx2    = (int*)p;
    cudaGetSymbolAddress(&p, g_keep);  int* keep    = (int*)p;
    cudaGetSymbolAddress(&p, g_slot1); int* slot1   = (int*)p;
    cudaGetSymbolAddress(&p, g_slot2); int* slot2   = (int*)p;
    cudaGetSymbolAddress(&p, g_g1);    float* g1    = (float*)p;
    cudaGetSymbolAddress(&p, g_g2);    float* g2    = (float*)p;
    cudaGetSymbolAddress(&p, g_rawsum);float* rawsum= (float*)p;
    cudaGetSymbolAddress(&p, g_cnt1);  float* cnt1  = (float*)p;
    cudaGetSymbolAddress(&p, g_lossbuf); float* lossbuf = (float*)p;
    cudaGetSymbolAddress(&p, g_whi);   __nv_bfloat16* whi = (__nv_bfloat16*)p;
    cudaGetSymbolAddress(&p, g_wlo);   __nv_bfloat16* wlo = (__nv_bfloat16*)p;

    cudaFuncSetAttribute(flash_kernel, cudaFuncAttributeMaxDynamicSharedMemorySize, FSM);
    cudaFuncSetAttribute(mma_gemm, cudaFuncAttributeMaxDynamicSharedMemorySize, MGSMEM);

    float* lossp = (out_size > TOK * Dn) ? (xout + (size_t)TOK * Dn) : lossbuf;

    unsigned k1a, k1b, k2a, k2b;
    { unsigned a = 0u, b = 0u; threefry2x32(0u, 42u, a, b); k1a = a; k1b = b; }
    { unsigned a = 0u, b = 1u; threefry2x32(0u, 42u, a, b); k2a = a; k2b = b; }

    const long long sXE  = (long long)Bn * CAPn * Dn;
    const long long sHID = (long long)Bn * CAPn * MOEHn;
    dim3 wb(32, 8);
#define NILB (__nv_bfloat16*)0
#define NILF (const float*)0

    // items: 0 memcpy, 1 wprep(qkv), 2 rmsnorm, 3 qkv gemm <- profiled at -s 5? keep layout
    cudaMemcpyAsync(xout, x, (size_t)TOK * Dn * sizeof(float),
                    cudaMemcpyDeviceToDevice, 0);
    wprep_kernel<<<dim3(96, 32, 3),  wb>>>(wqkv, whi + QKV_OFF, wlo + QKV_OFF,
                                           1024, 3072, 1024LL*3072, 1024LL*3072);
    rmsnorm_kernel<<<TOK, 256>>>(xout, ln, norm, normh, norml);
    mma_gemm<<<dim3(24, 32, 1), 256, MGSMEM>>>(
        normh, norml, whi + QKV_OFF, wlo + QKV_OFF,
        (float*)0, bigh, bigl, NILF, cosb, sinb, TOK, 3072, 1024, 0, 0, 0, 4);
    cudaMemsetAsync(lossp, 0, sizeof(float), 0);
    flash_kernel<<<dim3(16, 64), 128, FSM>>>(bigh, bigl, attnh, attnl);

    wprep_kernel<<<dim3(32, 32, 3),  wb>>>(wo,  whi + WO_OFF,  wlo + WO_OFF,
                                           1024, 1024, 1024LL*1024, 1024LL*1024);
    wprep_kernel<<<dim3(88, 32, 3),  wb>>>(w1,  whi + W1_OFF,  wlo + W1_OFF,
                                           1024, 2816, 1024LL*2816, 1024LL*2816);
    wprep_kernel<<<dim3(88, 32, 3),  wb>>>(w3,  whi + W3_OFF,  wlo + W3_OFF,
                                           1024, 2816, 1024LL*2816, 1024LL*2816);
    wprep_kernel<<<dim3(32, 88, 3),  wb>>>(w2,  whi + W2_OFF,  wlo + W2_OFF,
                                           2816, 1024, 2816LL*1024, 2816LL*1024);
    wprep_kernel<<<dim3(64, 32, 16), wb>>>(mw1, whi + MW1_OFF, wlo + MW1_OFF,
                                           1024, 2048, 1024LL*2048, 1024LL*2048);
    wprep_kernel<<<dim3(32, 64, 16), wb>>>(mw2, whi + MW2_OFF, wlo + MW2_OFF,
                                           2048, 1024, 2048LL*1024, 2048LL*1024);

    auto attn_tail = [&](int la) {
        mma_gemm<<<dim3(8, 32, 1), 256, MGSMEM>>>(
            attnh, attnl,
            whi + WO_OFF + (long long)la * 1048576,
            wlo + WO_OFF + (long long)la * 1048576,
            xout, NILB, NILB, NILF, NILF, NILF, TOK, 1024, 1024, 0, 0, 0, 1);
    };
    auto attn_layer = [&](int la, int lnidx) {
        rmsnorm_kernel<<<TOK, 256>>>(xout, ln + (size_t)lnidx * Dn, norm, normh, norml);
        mma_gemm<<<dim3(24, 32, 1), 256, MGSMEM>>>(
            normh, norml,
            whi + QKV_OFF + (long long)la * 3145728,
            wlo + QKV_OFF + (long long)la * 3145728,
            (float*)0, bigh, bigl, NILF, cosb, sinb, TOK, 3072, 1024, 0, 0, 0, 4);
        flash_kernel<<<dim3(16, 64), 128, FSM>>>(bigh, bigl, attnh, attnl);
        attn_tail(la);
    };
    auto mlp_layer = [&](int lm, int lnidx) {
        rmsnorm_kernel<<<TOK, 256>>>(xout, ln + (size_t)lnidx * Dn, norm, normh, norml);
        mma_gemm<<<dim3(22, 32, 1), 256, MGSMEM>>>(
            normh, norml,
            whi + W1_OFF + (long long)lm * 2883584,
            wlo + W1_OFF + (long long)lm * 2883584,
            h1, NILB, NILB, NILF, NILF, NILF, TOK, 2816, 1024, 0, 0, 0, 0);
        mma_gemm<<<dim3(22, 32, 1), 256, MGSMEM>>>(
            normh, norml,
            whi + W3_OFF + (long long)lm * 2883584,
            wlo + W3_OFF + (long long)lm * 2883584,
            (float*)0, hidh, hidl, h1, NILF, NILF, TOK, 2816, 1024, 0, 0, 0, 3);
        mma_gemm<<<dim3(8, 32, 1), 256, MGSMEM>>>(
            hidh, hidl,
            whi + W2_OFF + (long long)lm * 2883584,
            wlo + W2_OFF + (long long)lm * 2883584,
            xout, NILB, NILB, NILF, NILF, NILF, TOK, 1024, 2816, 0, 0, 0, 1);
    };
    auto moe_layer = [&](int lo, int lnidx, unsigned ka, unsigned kbb) {
        rmsnorm_kernel<<<TOK, 256>>>(xout, ln + (size_t)lnidx * Dn, norm, normh, norml);
        gate_kernel<<<TOK, 256>>>(norm, wg + (size_t)lo * Dn * NEn,
                                  raw, idx1, idx2, keep, g1, g2, ka, kbb);
        loss_sum_kernel<<<Bn * NEn, 256>>>(raw, idx1, rawsum, cnt1);
        slots_kernel<<<1, 256>>>(idx1, idx2, keep, slot1, slot2, rawsum, cnt1, lossp);
        scatter_kernel<<<TOK, 128>>>(normh, norml, slot1, slot2, xeh, xel);
        mma_gemm<<<dim3(16, 5, 8), 256, MGSMEM>>>(
            xeh, xel,
            whi + MW1_OFF + (long long)lo * 16777216,
            wlo + MW1_OFF + (long long)lo * 16777216,
            (float*)0, hidh, hidl, NILF, NILF, NILF,
            Bn * CAPn, MOEHn, 1024, sXE, 2097152LL, sHID, 2);
        mma_gemm<<<dim3(8, 5, 8), 256, MGSMEM>>>(
            hidh, hidl,
            whi + MW2_OFF + (long long)lo * 16777216,
            wlo + MW2_OFF + (long long)lo * 16777216,
            ye, NILB, NILB, NILF, NILF, NILF,
            Bn * CAPn, 1024, 2048, sHID, 2097152LL, sXE, 0);
        combine_kernel<<<TOK, 256>>>(ye, slot1, slot2, g1, g2, xout);
    };

    attn_tail(0);               // layer-0 rmsnorm/qkv/flash issued above
    mlp_layer(0, 1);
    moe_layer(0, 2, k1a, k1b);
    mlp_layer(1, 3);
    attn_layer(1, 4);
    moe_layer(1, 5, k2a, k2b);
    attn_layer(2, 6);
    mlp_layer(2, 7);
}